// round 2
// baseline (speedup 1.0000x reference)
#include <cuda_runtime.h>
#include <cuda_bf16.h>

#define N_NODES 100000
#define N_EDGES 1600000
#define D       128
#define D2      256
#define N_LAYERS 4

// ---------------- scratch (device globals: no allocation allowed) ----------------
__device__ float g_x   [(size_t)N_NODES * D];    // current node features
__device__ float g_skip[(size_t)N_NODES * D];    // x @ W_skip
__device__ float g_bgs [(size_t)N_NODES * D2];   // x @ W_fskip    (beta_s | gamma_s)
__device__ float g_h   [(size_t)N_NODES * D];    // x @ W_lin
__device__ float g_bg  [(size_t)N_NODES * D2];   // x @ W_film + b (beta | gamma)
__device__ float g_out [(size_t)N_NODES * D];    // self branch
__device__ float g_agg [(size_t)N_NODES * D];    // edge aggregation
__device__ float g_deginv[N_NODES];
__device__ int   g_deg   [N_NODES];
__device__ int   g_is64;                         // 1 if edge_index is int64, 0 if int32

// ---------------- edge-index dtype probe ----------------
// int64 data: every value in [0, N_NODES). int32 data misread as int64 packs two
// random indices (lo + hi*2^32): valid-looking only if hi==0 (p ~ 1e-5 per value).
__global__ void detect_kernel(const long long* __restrict__ ei) {
    if (threadIdx.x == 0 && blockIdx.x == 0) {
        int ok = 1;
        #pragma unroll
        for (int i = 0; i < 16; i++) {
            long long v = ei[i];
            if (v < 0 || v >= N_NODES) ok = 0;
        }
        g_is64 = ok;
    }
}

__device__ __forceinline__ int edge_at(const void* ei, size_t idx, int is64) {
    return is64 ? (int)((const long long*)ei)[idx] : ((const int*)ei)[idx];
}

// ---------------- small utility kernels ----------------
__global__ void zero_deg_kernel() {
    int i = blockIdx.x * blockDim.x + threadIdx.x;
    if (i < N_NODES) g_deg[i] = 0;
}

__global__ void count_deg_kernel(const void* __restrict__ ei) {
    int e = blockIdx.x * blockDim.x + threadIdx.x;
    if (e < N_EDGES) {
        int is64 = g_is64;
        int d = edge_at(ei, (size_t)N_EDGES + e, is64);
        atomicAdd(&g_deg[d], 1);
    }
}

__global__ void deginv_kernel() {
    int i = blockIdx.x * blockDim.x + threadIdx.x;
    if (i < N_NODES) {
        float d = (float)g_deg[i];
        g_deginv[i] = 1.0f / fmaxf(d, 1.0f);
    }
}

__global__ void copy_x_kernel(const float4* __restrict__ src) {
    int i = blockIdx.x * blockDim.x + threadIdx.x;
    if (i < N_NODES * (D / 4)) ((float4*)g_x)[i] = src[i];
}

// ---------------- SGEMM: C[M x N] = A[M x 128] @ B[128 x N] (+bias) -------------
// BM=BN=128, BK=16, TM=TN=8, 256 threads.
__global__ __launch_bounds__(256)
void sgemm_kernel(const float* __restrict__ A, const float* __restrict__ B,
                  const float* __restrict__ bias, float* __restrict__ C,
                  int M, int N) {
    constexpr int BM = 128, BN = 128, BK = 16, TM = 8, TN = 8;
    __shared__ float As[BK][BM + 4];
    __shared__ float Bs[BK][BN];

    const int tid = threadIdx.x;
    const int tx  = tid & 15;       // N direction (16)
    const int ty  = tid >> 4;       // M direction (16)
    const int rowBase = blockIdx.y * BM;
    const int colBase = blockIdx.x * BN;

    const int aRow  = tid >> 2;         // 0..63
    const int aCol4 = (tid & 3) * 4;    // 0,4,8,12
    const int bRow  = tid >> 5;         // 0..7
    const int bCol4 = (tid & 31) * 4;   // 0..124

    float acc[TM][TN];
    #pragma unroll
    for (int i = 0; i < TM; i++)
        #pragma unroll
        for (int j = 0; j < TN; j++) acc[i][j] = 0.0f;

    for (int k0 = 0; k0 < D; k0 += BK) {
        #pragma unroll
        for (int r = 0; r < BM; r += 64) {
            int row = rowBase + aRow + r;
            float4 v = make_float4(0.f, 0.f, 0.f, 0.f);
            if (row < M) v = *(const float4*)(A + (size_t)row * D + k0 + aCol4);
            As[aCol4 + 0][aRow + r] = v.x;
            As[aCol4 + 1][aRow + r] = v.y;
            As[aCol4 + 2][aRow + r] = v.z;
            As[aCol4 + 3][aRow + r] = v.w;
        }
        #pragma unroll
        for (int r = 0; r < BK; r += 8) {
            float4 v = *(const float4*)(B + (size_t)(k0 + bRow + r) * N + colBase + bCol4);
            *(float4*)&Bs[bRow + r][bCol4] = v;
        }
        __syncthreads();

        #pragma unroll
        for (int k = 0; k < BK; k++) {
            float af[TM], bf[TN];
            #pragma unroll
            for (int i = 0; i < TM; i++) af[i] = As[k][ty * TM + i];
            #pragma unroll
            for (int j = 0; j < TN; j++) bf[j] = Bs[k][tx * TN + j];
            #pragma unroll
            for (int i = 0; i < TM; i++)
                #pragma unroll
                for (int j = 0; j < TN; j++)
                    acc[i][j] = fmaf(af[i], bf[j], acc[i][j]);
        }
        __syncthreads();
    }

    #pragma unroll
    for (int i = 0; i < TM; i++) {
        int row = rowBase + ty * TM + i;
        if (row >= M) continue;
        #pragma unroll
        for (int j = 0; j < TN; j += 4) {
            int col = colBase + tx * TN + j;
            float4 v = make_float4(acc[i][j], acc[i][j + 1], acc[i][j + 2], acc[i][j + 3]);
            if (bias) {
                v.x += bias[col + 0]; v.y += bias[col + 1];
                v.z += bias[col + 2]; v.w += bias[col + 3];
            }
            *(float4*)(C + (size_t)row * N + col) = v;
        }
    }
}

// ---------------- self-FiLM branch + agg zeroing --------------------------------
__global__ void selffilm_kernel() {
    int i = blockIdx.x * blockDim.x + threadIdx.x;   // 0 .. N_NODES*32-1
    if (i >= N_NODES * (D / 4)) return;
    int node = i >> 5;
    int j    = i & 31;
    const float4* sk4  = (const float4*)g_skip;
    const float4* bgs4 = (const float4*)g_bgs;
    float4 s = sk4[i];
    float4 be = bgs4[(size_t)node * 64 + j];
    float4 ga = bgs4[(size_t)node * 64 + 32 + j];
    float4 o;
    o.x = fmaxf(fmaf(ga.x, s.x, be.x), 0.f);
    o.y = fmaxf(fmaf(ga.y, s.y, be.y), 0.f);
    o.z = fmaxf(fmaf(ga.z, s.z, be.z), 0.f);
    o.w = fmaxf(fmaf(ga.w, s.w, be.w), 0.f);
    ((float4*)g_out)[i] = o;
    ((float4*)g_agg)[i] = make_float4(0.f, 0.f, 0.f, 0.f);
}

// ---------------- edge phase: msg = relu(gamma[dst]*h[src]+beta[dst]) -----------
// One warp per edge; lane handles 4 floats; scatter via atomicAdd.
__global__ __launch_bounds__(256)
void edge_kernel(const void* __restrict__ ei) {
    int e = blockIdx.x * 8 + (threadIdx.x >> 5);
    if (e >= N_EDGES) return;
    int lane = threadIdx.x & 31;
    int is64 = g_is64;
    int s = edge_at(ei, (size_t)e, is64);
    int d = edge_at(ei, (size_t)N_EDGES + e, is64);
    const float4* h4  = (const float4*)g_h;
    const float4* bg4 = (const float4*)g_bg;
    float4 hv = h4[(size_t)s * 32 + lane];
    float4 be = bg4[(size_t)d * 64 + lane];
    float4 ga = bg4[(size_t)d * 64 + 32 + lane];
    float4 m;
    m.x = fmaxf(fmaf(ga.x, hv.x, be.x), 0.f);
    m.y = fmaxf(fmaf(ga.y, hv.y, be.y), 0.f);
    m.z = fmaxf(fmaf(ga.z, hv.z, be.z), 0.f);
    m.w = fmaxf(fmaf(ga.w, hv.w, be.w), 0.f);
    float* dst = g_agg + (size_t)d * D + lane * 4;
    atomicAdd(dst + 0, m.x);
    atomicAdd(dst + 1, m.y);
    atomicAdd(dst + 2, m.z);
    atomicAdd(dst + 3, m.w);
}

// ---------------- finalize: x_next = out + agg*deg_inv (+relu) ------------------
__global__ void finalize_kernel(float* __restrict__ dstp, int do_relu) {
    int i = blockIdx.x * blockDim.x + threadIdx.x;
    if (i >= N_NODES * (D / 4)) return;
    int node = i >> 5;
    float di = g_deginv[node];
    float4 o = ((const float4*)g_out)[i];
    float4 a = ((const float4*)g_agg)[i];
    float4 v;
    v.x = fmaf(a.x, di, o.x);
    v.y = fmaf(a.y, di, o.y);
    v.z = fmaf(a.z, di, o.z);
    v.w = fmaf(a.w, di, o.w);
    if (do_relu) {
        v.x = fmaxf(v.x, 0.f); v.y = fmaxf(v.y, 0.f);
        v.z = fmaxf(v.z, 0.f); v.w = fmaxf(v.w, 0.f);
    }
    ((float4*)dstp)[i] = v;
}

// ---------------- launch --------------------------------------------------------
extern "C" void kernel_launch(void* const* d_in, const int* in_sizes, int n_in,
                              void* d_out, int out_size) {
    const float* x_in    = (const float*)d_in[0];
    const void*  ei      = d_in[1];
    const float* W_lin   = (const float*)d_in[2];   // [4,128,128]
    const float* W_film  = (const float*)d_in[3];   // [4,128,256]
    const float* b_film  = (const float*)d_in[4];   // [4,256]
    const float* W_skip  = (const float*)d_in[5];   // [4,128,128]
    const float* W_fskip = (const float*)d_in[6];   // [4,128,256]
    float*       out     = (float*)d_out;

    float *px, *pskip, *pbgs, *ph, *pbg;
    cudaGetSymbolAddress((void**)&px,    g_x);
    cudaGetSymbolAddress((void**)&pskip, g_skip);
    cudaGetSymbolAddress((void**)&pbgs,  g_bgs);
    cudaGetSymbolAddress((void**)&ph,    g_h);
    cudaGetSymbolAddress((void**)&pbg,   g_bg);

    const int nvec = N_NODES * (D / 4);          // 3.2M float4
    const int vblocks = (nvec + 255) / 256;
    const int mtiles = (N_NODES + 127) / 128;    // 782

    detect_kernel<<<1, 32>>>((const long long*)ei);
    zero_deg_kernel<<<(N_NODES + 255) / 256, 256>>>();
    count_deg_kernel<<<(N_EDGES + 255) / 256, 256>>>(ei);
    deginv_kernel<<<(N_NODES + 255) / 256, 256>>>();
    copy_x_kernel<<<vblocks, 256>>>((const float4*)x_in);

    for (int l = 0; l < N_LAYERS; l++) {
        const float* wl  = W_lin   + (size_t)l * D * D;
        const float* wf  = W_film  + (size_t)l * D * D2;
        const float* bf  = b_film  + (size_t)l * D2;
        const float* ws  = W_skip  + (size_t)l * D * D;
        const float* wfs = W_fskip + (size_t)l * D * D2;

        sgemm_kernel<<<dim3(1, mtiles), 256>>>(px, ws,  nullptr, pskip, N_NODES, D);
        sgemm_kernel<<<dim3(2, mtiles), 256>>>(px, wfs, nullptr, pbgs,  N_NODES, D2);
        sgemm_kernel<<<dim3(1, mtiles), 256>>>(px, wl,  nullptr, ph,    N_NODES, D);
        sgemm_kernel<<<dim3(2, mtiles), 256>>>(px, wf,  bf,      pbg,   N_NODES, D2);

        selffilm_kernel<<<vblocks, 256>>>();
        edge_kernel<<<(N_EDGES + 7) / 8, 256>>>(ei);

        float* dstp = (l == N_LAYERS - 1) ? out : px;
        finalize_kernel<<<vblocks, 256>>>(dstp, l < N_LAYERS - 1 ? 1 : 0);
    }
}

// round 4
// speedup vs baseline: 1.7946x; 1.7946x over previous
#include <cuda_runtime.h>
#include <cuda_bf16.h>

#define N_NODES 100000
#define N_EDGES 1600000
#define D       128
#define DZ      768          // fused output width: skip|beta_s|gamma_s|h|beta|gamma
#define N_LAYERS 4

// ---------------- scratch (device globals: no allocation allowed) ----------------
__device__ float g_x    [(size_t)N_NODES * D];    // current node features
__device__ float g_z    [(size_t)N_NODES * DZ];   // fused GEMM output
__device__ float g_wpack[(size_t)N_LAYERS * D * DZ];
__device__ float g_bpack[(size_t)N_LAYERS * DZ];
__device__ float g_deginv[N_NODES];
__device__ int   g_deg   [N_NODES];
__device__ int   g_scan  [N_NODES];
__device__ int   g_bsum  [512];
__device__ int   g_rowptr[N_NODES + 1];
__device__ int   g_fill  [N_NODES];
__device__ int   g_esrc  [N_EDGES];
__device__ int   g_is64;

// ---------------- edge-index dtype probe ----------------
__global__ void detect_kernel(const long long* __restrict__ ei) {
    if (threadIdx.x == 0 && blockIdx.x == 0) {
        int ok = 1;
        #pragma unroll
        for (int i = 0; i < 16; i++) {
            long long v = ei[i];
            if (v < 0 || v >= N_NODES) ok = 0;
        }
        g_is64 = ok;
    }
}

__device__ __forceinline__ int edge_at(const void* ei, size_t idx, int is64) {
    return is64 ? (int)((const long long*)ei)[idx] : ((const int*)ei)[idx];
}

// ---------------- degree + CSR build ----------------
__global__ void zero_deg_kernel() {
    int i = blockIdx.x * blockDim.x + threadIdx.x;
    if (i < N_NODES) g_deg[i] = 0;
}

__global__ void count_deg_kernel(const void* __restrict__ ei) {
    int e = blockIdx.x * blockDim.x + threadIdx.x;
    if (e < N_EDGES) {
        int d = edge_at(ei, (size_t)N_EDGES + e, g_is64);
        atomicAdd(&g_deg[d], 1);
    }
}

// per-block inclusive scan of deg (256 elems/block)
__global__ void scan1_kernel() {
    __shared__ int s[256];
    int tid = threadIdx.x;
    int i = blockIdx.x * 256 + tid;
    int v = (i < N_NODES) ? g_deg[i] : 0;
    s[tid] = v; __syncthreads();
    #pragma unroll
    for (int off = 1; off < 256; off <<= 1) {
        int t = (tid >= off) ? s[tid - off] : 0;
        __syncthreads();
        s[tid] += t;
        __syncthreads();
    }
    if (i < N_NODES) g_scan[i] = s[tid];
    if (tid == 255) g_bsum[blockIdx.x] = s[255];
}

// single-block inclusive scan of 391 block sums
__global__ void scan2_kernel(int nblk) {
    __shared__ int s[512];
    int tid = threadIdx.x;
    int v = (tid < nblk) ? g_bsum[tid] : 0;
    s[tid] = v; __syncthreads();
    #pragma unroll
    for (int off = 1; off < 512; off <<= 1) {
        int t = (tid >= off) ? s[tid - off] : 0;
        __syncthreads();
        s[tid] += t;
        __syncthreads();
    }
    if (tid < nblk) g_bsum[tid] = s[tid];
}

// rowptr[i] = exclusive prefix; also zero fill counters, compute deginv
__global__ void rowptr_kernel() {
    int i = blockIdx.x * blockDim.x + threadIdx.x;
    if (i < N_NODES) {
        int blk = i >> 8;
        int off = (blk > 0) ? g_bsum[blk - 1] : 0;
        g_rowptr[i] = g_scan[i] - g_deg[i] + off;
        g_fill[i] = 0;
        g_deginv[i] = 1.0f / fmaxf((float)g_deg[i], 1.0f);
    }
    if (i == 0) g_rowptr[N_NODES] = N_EDGES;
}

__global__ void scatter_kernel(const void* __restrict__ ei) {
    int e = blockIdx.x * blockDim.x + threadIdx.x;
    if (e < N_EDGES) {
        int is64 = g_is64;
        int s = edge_at(ei, (size_t)e, is64);
        int d = edge_at(ei, (size_t)N_EDGES + e, is64);
        int pos = g_rowptr[d] + atomicAdd(&g_fill[d], 1);
        g_esrc[pos] = s;
    }
}

__global__ void copy_x_kernel(const float4* __restrict__ src) {
    int i = blockIdx.x * blockDim.x + threadIdx.x;
    if (i < N_NODES * (D / 4)) ((float4*)g_x)[i] = src[i];
}

// ---------------- weight/bias packing ----------------
// fused cols: [0,128)=W_skip  [128,384)=W_fskip  [384,512)=W_lin  [512,768)=W_film
__global__ void wpack_kernel(const float* __restrict__ W_lin,
                             const float* __restrict__ W_film,
                             const float* __restrict__ W_skip,
                             const float* __restrict__ W_fskip) {
    int i = blockIdx.x * blockDim.x + threadIdx.x;   // [0, 4*128*768)
    if (i >= N_LAYERS * D * DZ) return;
    int c = i % DZ;
    int k = (i / DZ) % D;
    int l = i / (DZ * D);
    float v;
    if (c < 128)      v = W_skip [((size_t)l * D + k) * 128 + c];
    else if (c < 384) v = W_fskip[((size_t)l * D + k) * 256 + (c - 128)];
    else if (c < 512) v = W_lin  [((size_t)l * D + k) * 128 + (c - 384)];
    else              v = W_film [((size_t)l * D + k) * 256 + (c - 512)];
    g_wpack[i] = v;
}

__global__ void bpack_kernel(const float* __restrict__ b_film) {
    int i = blockIdx.x * blockDim.x + threadIdx.x;   // [0, 4*768)
    if (i >= N_LAYERS * DZ) return;
    int c = i % DZ;
    int l = i / DZ;
    g_bpack[i] = (c >= 512) ? b_film[(size_t)l * 256 + (c - 512)] : 0.0f;
}

// ---------------- fused SGEMM: g_z[M x 768] = A[M x 128] @ W[128 x 768] + bias --
// BM=BN=128, BK=16, TM=TN=8, 256 threads, double-buffered smem.
__global__ __launch_bounds__(256)
void sgemm_kernel(const float* __restrict__ A, const float* __restrict__ B,
                  const float* __restrict__ bias, float* __restrict__ C) {
    constexpr int BM = 128, BN = 128, BK = 16, TM = 8, TN = 8;
    constexpr int M = N_NODES, N = DZ;
    __shared__ float As[2][BK][BM + 4];
    __shared__ float Bs[2][BK][BN];

    const int tid = threadIdx.x;
    const int tx  = tid & 15;
    const int ty  = tid >> 4;
    const int rowBase = blockIdx.y * BM;
    const int colBase = blockIdx.x * BN;

    const int aRow  = tid >> 2;         // 0..63
    const int aCol4 = (tid & 3) * 4;    // 0,4,8,12
    const int bRow  = tid >> 5;         // 0..7
    const int bCol4 = (tid & 31) * 4;   // 0..124

    float acc[TM][TN];
    #pragma unroll
    for (int i = 0; i < TM; i++)
        #pragma unroll
        for (int j = 0; j < TN; j++) acc[i][j] = 0.0f;

    // ---- load tile 0 into buffer 0
    {
        #pragma unroll
        for (int r = 0; r < BM; r += 64) {
            int row = rowBase + aRow + r;
            float4 v = make_float4(0.f, 0.f, 0.f, 0.f);
            if (row < M) v = *(const float4*)(A + (size_t)row * D + aCol4);
            As[0][aCol4 + 0][aRow + r] = v.x;
            As[0][aCol4 + 1][aRow + r] = v.y;
            As[0][aCol4 + 2][aRow + r] = v.z;
            As[0][aCol4 + 3][aRow + r] = v.w;
        }
        #pragma unroll
        for (int r = 0; r < BK; r += 8) {
            float4 v = *(const float4*)(B + (size_t)(bRow + r) * N + colBase + bCol4);
            *(float4*)&Bs[0][bRow + r][bCol4] = v;
        }
    }
    __syncthreads();

    #pragma unroll
    for (int t = 0; t < D / BK; t++) {
        const int cur = t & 1;
        float4 pa0, pa1, pb0, pb1;
        if (t < D / BK - 1) {
            const int k0 = (t + 1) * BK;
            int row0 = rowBase + aRow;
            int row1 = rowBase + aRow + 64;
            pa0 = make_float4(0.f, 0.f, 0.f, 0.f);
            pa1 = make_float4(0.f, 0.f, 0.f, 0.f);
            if (row0 < M) pa0 = *(const float4*)(A + (size_t)row0 * D + k0 + aCol4);
            if (row1 < M) pa1 = *(const float4*)(A + (size_t)row1 * D + k0 + aCol4);
            pb0 = *(const float4*)(B + (size_t)(k0 + bRow) * N + colBase + bCol4);
            pb1 = *(const float4*)(B + (size_t)(k0 + bRow + 8) * N + colBase + bCol4);
        }

        #pragma unroll
        for (int k = 0; k < BK; k++) {
            float af[TM], bf[TN];
            #pragma unroll
            for (int i = 0; i < TM; i++) af[i] = As[cur][k][ty * TM + i];
            #pragma unroll
            for (int j = 0; j < TN; j++) bf[j] = Bs[cur][k][tx * TN + j];
            #pragma unroll
            for (int i = 0; i < TM; i++)
                #pragma unroll
                for (int j = 0; j < TN; j++)
                    acc[i][j] = fmaf(af[i], bf[j], acc[i][j]);
        }

        if (t < D / BK - 1) {
            const int nxt = 1 - cur;
            As[nxt][aCol4 + 0][aRow]      = pa0.x;
            As[nxt][aCol4 + 1][aRow]      = pa0.y;
            As[nxt][aCol4 + 2][aRow]      = pa0.z;
            As[nxt][aCol4 + 3][aRow]      = pa0.w;
            As[nxt][aCol4 + 0][aRow + 64] = pa1.x;
            As[nxt][aCol4 + 1][aRow + 64] = pa1.y;
            As[nxt][aCol4 + 2][aRow + 64] = pa1.z;
            As[nxt][aCol4 + 3][aRow + 64] = pa1.w;
            *(float4*)&Bs[nxt][bRow][bCol4]     = pb0;
            *(float4*)&Bs[nxt][bRow + 8][bCol4] = pb1;
            __syncthreads();
        }
    }

    #pragma unroll
    for (int i = 0; i < TM; i++) {
        int row = rowBase + ty * TM + i;
        if (row >= M) continue;
        #pragma unroll
        for (int j = 0; j < TN; j += 4) {
            int col = colBase + tx * TN + j;
            float4 v = make_float4(acc[i][j], acc[i][j + 1], acc[i][j + 2], acc[i][j + 3]);
            v.x += bias[col + 0]; v.y += bias[col + 1];
            v.z += bias[col + 2]; v.w += bias[col + 3];
            *(float4*)(C + (size_t)row * N + col) = v;
        }
    }
}

// ---------------- fused node kernel: self-FiLM + CSR aggregation + finalize -----
// One warp per node. z row (float4 units, 192/row): skip@0 beta_s@32 gamma_s@64
// h@96 beta@128 gamma@160.
__global__ __launch_bounds__(256)
void node_kernel(float* __restrict__ dstp, int do_relu) {
    int n = blockIdx.x * 8 + (threadIdx.x >> 5);
    if (n >= N_NODES) return;
    int lane = threadIdx.x & 31;
    const float4* z4 = (const float4*)g_z;
    size_t rb = (size_t)n * 192;

    float4 skip = z4[rb + lane];
    float4 bs   = z4[rb + 32 + lane];
    float4 gs   = z4[rb + 64 + lane];
    float4 be   = z4[rb + 128 + lane];
    float4 ga   = z4[rb + 160 + lane];

    float4 acc = make_float4(0.f, 0.f, 0.f, 0.f);
    int e  = g_rowptr[n];
    int e1 = g_rowptr[n + 1];
    for (; e + 1 < e1; e += 2) {
        int s0 = g_esrc[e];
        int s1 = g_esrc[e + 1];
        float4 h0 = z4[(size_t)s0 * 192 + 96 + lane];
        float4 h1 = z4[(size_t)s1 * 192 + 96 + lane];
        acc.x += fmaxf(fmaf(ga.x, h0.x, be.x), 0.f) + fmaxf(fmaf(ga.x, h1.x, be.x), 0.f);
        acc.y += fmaxf(fmaf(ga.y, h0.y, be.y), 0.f) + fmaxf(fmaf(ga.y, h1.y, be.y), 0.f);
        acc.z += fmaxf(fmaf(ga.z, h0.z, be.z), 0.f) + fmaxf(fmaf(ga.z, h1.z, be.z), 0.f);
        acc.w += fmaxf(fmaf(ga.w, h0.w, be.w), 0.f) + fmaxf(fmaf(ga.w, h1.w, be.w), 0.f);
    }
    if (e < e1) {
        int s0 = g_esrc[e];
        float4 h0 = z4[(size_t)s0 * 192 + 96 + lane];
        acc.x += fmaxf(fmaf(ga.x, h0.x, be.x), 0.f);
        acc.y += fmaxf(fmaf(ga.y, h0.y, be.y), 0.f);
        acc.z += fmaxf(fmaf(ga.z, h0.z, be.z), 0.f);
        acc.w += fmaxf(fmaf(ga.w, h0.w, be.w), 0.f);
    }

    float di = g_deginv[n];
    float4 o;
    o.x = fmaxf(fmaf(gs.x, skip.x, bs.x), 0.f) + acc.x * di;
    o.y = fmaxf(fmaf(gs.y, skip.y, bs.y), 0.f) + acc.y * di;
    o.z = fmaxf(fmaf(gs.z, skip.z, bs.z), 0.f) + acc.z * di;
    o.w = fmaxf(fmaf(gs.w, skip.w, bs.w), 0.f) + acc.w * di;
    if (do_relu) {
        o.x = fmaxf(o.x, 0.f); o.y = fmaxf(o.y, 0.f);
        o.z = fmaxf(o.z, 0.f); o.w = fmaxf(o.w, 0.f);
    }
    ((float4*)dstp)[(size_t)n * 32 + lane] = o;
}

// ---------------- launch --------------------------------------------------------
extern "C" void kernel_launch(void* const* d_in, const int* in_sizes, int n_in,
                              void* d_out, int out_size) {
    const float* x_in    = (const float*)d_in[0];
    const void*  ei      = d_in[1];
    const float* W_lin   = (const float*)d_in[2];
    const float* W_film  = (const float*)d_in[3];
    const float* b_film  = (const float*)d_in[4];
    const float* W_skip  = (const float*)d_in[5];
    const float* W_fskip = (const float*)d_in[6];
    float*       out     = (float*)d_out;

    float *px, *pz, *pw, *pb;
    cudaGetSymbolAddress((void**)&px, g_x);
    cudaGetSymbolAddress((void**)&pz, g_z);
    cudaGetSymbolAddress((void**)&pw, g_wpack);
    cudaGetSymbolAddress((void**)&pb, g_bpack);

    const int nvec = N_NODES * (D / 4);
    const int vblocks = (nvec + 255) / 256;
    const int nodeb = (N_NODES + 255) / 256;      // 391
    const int edgeb = (N_EDGES + 255) / 256;      // 6250
    const int mtiles = (N_NODES + 127) / 128;     // 782

    detect_kernel<<<1, 32>>>((const long long*)ei);
    zero_deg_kernel<<<nodeb, 256>>>();
    count_deg_kernel<<<edgeb, 256>>>(ei);
    scan1_kernel<<<nodeb, 256>>>();
    scan2_kernel<<<1, 512>>>(nodeb);
    rowptr_kernel<<<nodeb, 256>>>();
    scatter_kernel<<<edgeb, 256>>>(ei);
    copy_x_kernel<<<vblocks, 256>>>((const float4*)x_in);
    wpack_kernel<<<(N_LAYERS * D * DZ + 255) / 256, 256>>>(W_lin, W_film, W_skip, W_fskip);
    bpack_kernel<<<(N_LAYERS * DZ + 255) / 256, 256>>>(b_film);

    for (int l = 0; l < N_LAYERS; l++) {
        sgemm_kernel<<<dim3(DZ / 128, mtiles), 256>>>(px, pw + (size_t)l * D * DZ,
                                                      pb + (size_t)l * DZ, pz);
        float* dstp = (l == N_LAYERS - 1) ? out : px;
        node_kernel<<<(N_NODES + 7) / 8, 256>>>(dstp, l < N_LAYERS - 1 ? 1 : 0);
    }
}

// round 7
// speedup vs baseline: 2.3933x; 1.3336x over previous
#include <cuda_runtime.h>
#include <cuda_bf16.h>
#include <cstdint>

#define N_NODES 100000
#define N_EDGES 1600000
#define D       128
#define DZ      768          // fused output width: skip|beta_s|gamma_s|h|beta|gamma
#define N_LAYERS 4

// ---------------- scratch (device globals: no allocation allowed) ----------------
__device__ float g_x    [(size_t)N_NODES * D];
__device__ float g_z    [(size_t)N_NODES * DZ];
__device__ __nv_bfloat16 g_wthi[(size_t)N_LAYERS * DZ * D];   // W^T hi  [l][n][k]
__device__ __nv_bfloat16 g_wtlo[(size_t)N_LAYERS * DZ * D];   // W^T lo
__device__ float g_bpack[(size_t)N_LAYERS * DZ];
__device__ float g_deginv[N_NODES];
__device__ int   g_deg   [N_NODES];
__device__ int   g_scan  [N_NODES];
__device__ int   g_bsum  [512];
__device__ int   g_rowptr[N_NODES + 1];
__device__ int   g_fill  [N_NODES];
__device__ int   g_esrc  [N_EDGES];
__device__ int   g_is64;

// ---------------- PTX helpers ----------------
__device__ __forceinline__ uint32_t smem_u32(const void* p) {
    uint32_t a;
    asm("{ .reg .u64 t; cvta.to.shared.u64 t, %1; cvt.u32.u64 %0, t; }" : "=r"(a) : "l"(p));
    return a;
}
__device__ __forceinline__ void ldsm_x4(uint32_t addr, uint32_t* r) {
    asm volatile("ldmatrix.sync.aligned.m8n8.x4.shared.b16 {%0,%1,%2,%3}, [%4];"
                 : "=r"(r[0]), "=r"(r[1]), "=r"(r[2]), "=r"(r[3]) : "r"(addr));
}
__device__ __forceinline__ void mma_bf16(float* c, const uint32_t* a, const uint32_t* b) {
    asm volatile(
        "mma.sync.aligned.m16n8k16.row.col.f32.bf16.bf16.f32 "
        "{%0,%1,%2,%3}, {%4,%5,%6,%7}, {%8,%9}, {%0,%1,%2,%3};"
        : "+f"(c[0]), "+f"(c[1]), "+f"(c[2]), "+f"(c[3])
        : "r"(a[0]), "r"(a[1]), "r"(a[2]), "r"(a[3]), "r"(b[0]), "r"(b[1]));
}

// ---------------- edge-index dtype probe ----------------
__global__ void detect_kernel(const long long* __restrict__ ei) {
    if (threadIdx.x == 0 && blockIdx.x == 0) {
        int ok = 1;
        #pragma unroll
        for (int i = 0; i < 16; i++) {
            long long v = ei[i];
            if (v < 0 || v >= N_NODES) ok = 0;
        }
        g_is64 = ok;
    }
}
__device__ __forceinline__ int edge_at(const void* ei, size_t idx, int is64) {
    return is64 ? (int)((const long long*)ei)[idx] : ((const int*)ei)[idx];
}

// ---------------- degree + CSR build ----------------
__global__ void zero_deg_kernel() {
    int i = blockIdx.x * blockDim.x + threadIdx.x;
    if (i < N_NODES) g_deg[i] = 0;
}
__global__ void count_deg_kernel(const void* __restrict__ ei) {
    int e = blockIdx.x * blockDim.x + threadIdx.x;
    if (e < N_EDGES) atomicAdd(&g_deg[edge_at(ei, (size_t)N_EDGES + e, g_is64)], 1);
}
__global__ void scan1_kernel() {
    __shared__ int s[256];
    int tid = threadIdx.x, i = blockIdx.x * 256 + tid;
    int v = (i < N_NODES) ? g_deg[i] : 0;
    s[tid] = v; __syncthreads();
    #pragma unroll
    for (int off = 1; off < 256; off <<= 1) {
        int t = (tid >= off) ? s[tid - off] : 0;
        __syncthreads(); s[tid] += t; __syncthreads();
    }
    if (i < N_NODES) g_scan[i] = s[tid];
    if (tid == 255) g_bsum[blockIdx.x] = s[255];
}
__global__ void scan2_kernel(int nblk) {
    __shared__ int s[512];
    int tid = threadIdx.x;
    s[tid] = (tid < nblk) ? g_bsum[tid] : 0; __syncthreads();
    #pragma unroll
    for (int off = 1; off < 512; off <<= 1) {
        int t = (tid >= off) ? s[tid - off] : 0;
        __syncthreads(); s[tid] += t; __syncthreads();
    }
    if (tid < nblk) g_bsum[tid] = s[tid];
}
__global__ void rowptr_kernel() {
    int i = blockIdx.x * blockDim.x + threadIdx.x;
    if (i < N_NODES) {
        int blk = i >> 8;
        int off = (blk > 0) ? g_bsum[blk - 1] : 0;
        g_rowptr[i] = g_scan[i] - g_deg[i] + off;
        g_fill[i] = 0;
        g_deginv[i] = 1.0f / fmaxf((float)g_deg[i], 1.0f);
    }
    if (i == 0) g_rowptr[N_NODES] = N_EDGES;
}
__global__ void scatter_kernel(const void* __restrict__ ei) {
    int e = blockIdx.x * blockDim.x + threadIdx.x;
    if (e < N_EDGES) {
        int is64 = g_is64;
        int s = edge_at(ei, (size_t)e, is64);
        int d = edge_at(ei, (size_t)N_EDGES + e, is64);
        g_esrc[g_rowptr[d] + atomicAdd(&g_fill[d], 1)] = s;
    }
}
__global__ void copy_x_kernel(const float4* __restrict__ src) {
    int i = blockIdx.x * blockDim.x + threadIdx.x;
    if (i < N_NODES * (D / 4)) ((float4*)g_x)[i] = src[i];
}

// ---------------- weight packing: W^T hi/lo bf16 split -------------------------
// fused cols: [0,128)=W_skip [128,384)=W_fskip [384,512)=W_lin [512,768)=W_film
__global__ void wpack_kernel(const float* __restrict__ W_lin,
                             const float* __restrict__ W_film,
                             const float* __restrict__ W_skip,
                             const float* __restrict__ W_fskip) {
    int i = blockIdx.x * blockDim.x + threadIdx.x;   // [0, 4*768*128)
    if (i >= N_LAYERS * DZ * D) return;
    int k = i % D;
    int n = (i / D) % DZ;
    int l = i / (D * DZ);
    float v;
    if (n < 128)      v = W_skip [((size_t)l * D + k) * 128 + n];
    else if (n < 384) v = W_fskip[((size_t)l * D + k) * 256 + (n - 128)];
    else if (n < 512) v = W_lin  [((size_t)l * D + k) * 128 + (n - 384)];
    else              v = W_film [((size_t)l * D + k) * 256 + (n - 512)];
    __nv_bfloat16 hi = __float2bfloat16_rn(v);
    __nv_bfloat16 lo = __float2bfloat16_rn(v - __bfloat162float(hi));
    g_wthi[i] = hi;
    g_wtlo[i] = lo;
}
__global__ void bpack_kernel(const float* __restrict__ b_film) {
    int i = blockIdx.x * blockDim.x + threadIdx.x;
    if (i >= N_LAYERS * DZ) return;
    int c = i % DZ, l = i / DZ;
    g_bpack[i] = (c >= 512) ? b_film[(size_t)l * 256 + (c - 512)] : 0.0f;
}

// ---------------- mma.sync bf16 GEMM: z tile [128x128] = A @ W^T + bias --------
// 3 passes: Ahi*Bhi + Ahi*Blo + Alo*Bhi, fp32 accum. K=128 smem-resident.
// Smem rows: 128 k-elems bf16 = 256B = 16 chunks of 16B; chunk swizzle ^ (row&7).
#define OFF_AHI  0
#define OFF_ALO  32768
#define OFF_BHI  65536
#define OFF_BLO  98304
#define SMEM_REQ 131072

__global__ __launch_bounds__(256, 1)
void gemm_mma_kernel(const float* __restrict__ A,
                     const __nv_bfloat16* __restrict__ Bhi,
                     const __nv_bfloat16* __restrict__ Blo,
                     const float* __restrict__ bias, float* __restrict__ C) {
    extern __shared__ char sm[];
    uint32_t sb = smem_u32(sm);
    int tid = threadIdx.x, wid = tid >> 5, lane = tid & 31;
    int row0 = blockIdx.y * 128;
    int n0   = blockIdx.x * 128;

    // ---- A loader: split fp32 -> bf16 hi/lo. thread = (row=tid/2, half=tid&1)
    {
        int r = tid >> 1, h = tid & 1;
        int grow = row0 + r;
        uint32_t rbase = r * 256;
        int r7 = r & 7;
        if (grow < N_NODES) {
            const float4* ap = (const float4*)(A + (size_t)grow * D + h * 64);
            #pragma unroll
            for (int it = 0; it < 8; it++) {
                float4 f0 = ap[it * 2], f1 = ap[it * 2 + 1];
                float f[8] = {f0.x, f0.y, f0.z, f0.w, f1.x, f1.y, f1.z, f1.w};
                __nv_bfloat16 hi8[8], lo8[8];
                #pragma unroll
                for (int q = 0; q < 8; q++) {
                    hi8[q] = __float2bfloat16_rn(f[q]);
                    lo8[q] = __float2bfloat16_rn(f[q] - __bfloat162float(hi8[q]));
                }
                int kc = h * 8 + it;
                uint32_t off = rbase + (uint32_t)((kc ^ r7) << 4);
                *(uint4*)(sm + OFF_AHI + off) = *(const uint4*)hi8;
                *(uint4*)(sm + OFF_ALO + off) = *(const uint4*)lo8;
            }
        } else {
            uint4 z = make_uint4(0, 0, 0, 0);
            #pragma unroll
            for (int it = 0; it < 8; it++) {
                int kc = h * 8 + it;
                uint32_t off = rbase + (uint32_t)((kc ^ r7) << 4);
                *(uint4*)(sm + OFF_AHI + off) = z;
                *(uint4*)(sm + OFF_ALO + off) = z;
            }
        }
    }
    // ---- B loader: copy prepacked bf16 hi/lo rows n0..n0+127
    {
        int n = tid >> 1, h = tid & 1;
        const uint4* bh = (const uint4*)(Bhi + (size_t)(n0 + n) * D + h * 64);
        const uint4* bl = (const uint4*)(Blo + (size_t)(n0 + n) * D + h * 64);
        uint32_t nb = n * 256;
        int n7 = n & 7;
        #pragma unroll
        for (int it = 0; it < 8; it++) {
            int kc = h * 8 + it;
            uint32_t off = nb + (uint32_t)((kc ^ n7) << 4);
            *(uint4*)(sm + OFF_BHI + off) = bh[it];
            *(uint4*)(sm + OFF_BLO + off) = bl[it];
        }
    }
    __syncthreads();

    // warp grid: 4 (M) x 2 (N); warp tile 32 rows x 64 cols
    int warpM = wid & 3, warpN = wid >> 2;
    float acc[2][8][4];
    #pragma unroll
    for (int mt = 0; mt < 2; mt++)
        #pragma unroll
        for (int nt = 0; nt < 8; nt++)
            #pragma unroll
            for (int q = 0; q < 4; q++) acc[mt][nt][q] = 0.0f;

    const int laneA_m   = lane & 15;
    const int laneA_kad = lane >> 4;                       // 0/1
    const int laneB_n   = (lane & 7) + ((lane & 16) ? 8 : 0);
    const int laneB_kad = (lane >> 3) & 1;

    #pragma unroll 1
    for (int pass = 0; pass < 3; pass++) {
        uint32_t abase = sb + (pass == 2 ? OFF_ALO : OFF_AHI);
        uint32_t bbase = sb + (pass == 1 ? OFF_BLO : OFF_BHI);
        #pragma unroll
        for (int ks = 0; ks < 8; ks++) {
            uint32_t af[2][4];
            #pragma unroll
            for (int mt = 0; mt < 2; mt++) {
                int m = warpM * 32 + mt * 16 + laneA_m;
                int kc = ks * 2 + laneA_kad;
                uint32_t ad = abase + m * 256 + (uint32_t)(((kc ^ (m & 7))) << 4);
                ldsm_x4(ad, af[mt]);
            }
            uint32_t bfr[8][2];
            #pragma unroll
            for (int g = 0; g < 4; g++) {
                int n = warpN * 64 + g * 16 + laneB_n;
                int kc = ks * 2 + laneB_kad;
                uint32_t bd = bbase + n * 256 + (uint32_t)(((kc ^ (n & 7))) << 4);
                uint32_t r[4];
                ldsm_x4(bd, r);
                bfr[g * 2][0] = r[0]; bfr[g * 2][1] = r[1];
                bfr[g * 2 + 1][0] = r[2]; bfr[g * 2 + 1][1] = r[3];
            }
            #pragma unroll
            for (int mt = 0; mt < 2; mt++)
                #pragma unroll
                for (int nt = 0; nt < 8; nt++)
                    mma_bf16(acc[mt][nt], af[mt], bfr[nt]);
        }
    }

    // ---- epilogue: c0,c1 -> (row, col..col+1); c2,c3 -> (row+8)
    int rbase = row0 + warpM * 32 + (lane >> 2);
    int cbase = n0 + warpN * 64 + (lane & 3) * 2;
    #pragma unroll
    for (int mt = 0; mt < 2; mt++) {
        #pragma unroll
        for (int nt = 0; nt < 8; nt++) {
            int col = cbase + nt * 8;
            float b0 = bias[col], b1 = bias[col + 1];
            int r1 = rbase + mt * 16;
            if (r1 < N_NODES) {
                float2 v = make_float2(acc[mt][nt][0] + b0, acc[mt][nt][1] + b1);
                *(float2*)(C + (size_t)r1 * DZ + col) = v;
            }
            int r2 = r1 + 8;
            if (r2 < N_NODES) {
                float2 v = make_float2(acc[mt][nt][2] + b0, acc[mt][nt][3] + b1);
                *(float2*)(C + (size_t)r2 * DZ + col) = v;
            }
        }
    }
}

// ---------------- fused node kernel (unchanged from R4 pass) --------------------
__global__ __launch_bounds__(256)
void node_kernel(float* __restrict__ dstp, int do_relu) {
    int n = blockIdx.x * 8 + (threadIdx.x >> 5);
    if (n >= N_NODES) return;
    int lane = threadIdx.x & 31;
    const float4* z4 = (const float4*)g_z;
    size_t rb = (size_t)n * 192;

    float4 skip = z4[rb + lane];
    float4 bs   = z4[rb + 32 + lane];
    float4 gs   = z4[rb + 64 + lane];
    float4 be   = z4[rb + 128 + lane];
    float4 ga   = z4[rb + 160 + lane];

    float4 acc = make_float4(0.f, 0.f, 0.f, 0.f);
    int e  = g_rowptr[n];
    int e1 = g_rowptr[n + 1];
    for (; e + 1 < e1; e += 2) {
        int s0 = g_esrc[e];
        int s1 = g_esrc[e + 1];
        float4 h0 = z4[(size_t)s0 * 192 + 96 + lane];
        float4 h1 = z4[(size_t)s1 * 192 + 96 + lane];
        acc.x += fmaxf(fmaf(ga.x, h0.x, be.x), 0.f) + fmaxf(fmaf(ga.x, h1.x, be.x), 0.f);
        acc.y += fmaxf(fmaf(ga.y, h0.y, be.y), 0.f) + fmaxf(fmaf(ga.y, h1.y, be.y), 0.f);
        acc.z += fmaxf(fmaf(ga.z, h0.z, be.z), 0.f) + fmaxf(fmaf(ga.z, h1.z, be.z), 0.f);
        acc.w += fmaxf(fmaf(ga.w, h0.w, be.w), 0.f) + fmaxf(fmaf(ga.w, h1.w, be.w), 0.f);
    }
    if (e < e1) {
        int s0 = g_esrc[e];
        float4 h0 = z4[(size_t)s0 * 192 + 96 + lane];
        acc.x += fmaxf(fmaf(ga.x, h0.x, be.x), 0.f);
        acc.y += fmaxf(fmaf(ga.y, h0.y, be.y), 0.f);
        acc.z += fmaxf(fmaf(ga.z, h0.z, be.z), 0.f);
        acc.w += fmaxf(fmaf(ga.w, h0.w, be.w), 0.f);
    }

    float di = g_deginv[n];
    float4 o;
    o.x = fmaxf(fmaf(gs.x, skip.x, bs.x), 0.f) + acc.x * di;
    o.y = fmaxf(fmaf(gs.y, skip.y, bs.y), 0.f) + acc.y * di;
    o.z = fmaxf(fmaf(gs.z, skip.z, bs.z), 0.f) + acc.z * di;
    o.w = fmaxf(fmaf(gs.w, skip.w, bs.w), 0.f) + acc.w * di;
    if (do_relu) {
        o.x = fmaxf(o.x, 0.f); o.y = fmaxf(o.y, 0.f);
        o.z = fmaxf(o.z, 0.f); o.w = fmaxf(o.w, 0.f);
    }
    ((float4*)dstp)[(size_t)n * 32 + lane] = o;
}

// ---------------- launch --------------------------------------------------------
extern "C" void kernel_launch(void* const* d_in, const int* in_sizes, int n_in,
                              void* d_out, int out_size) {
    const float* x_in    = (const float*)d_in[0];
    const void*  ei      = d_in[1];
    const float* W_lin   = (const float*)d_in[2];
    const float* W_film  = (const float*)d_in[3];
    const float* b_film  = (const float*)d_in[4];
    const float* W_skip  = (const float*)d_in[5];
    const float* W_fskip = (const float*)d_in[6];
    float*       out     = (float*)d_out;

    float *px, *pz, *pb;
    __nv_bfloat16 *pwh, *pwl;
    cudaGetSymbolAddress((void**)&px,  g_x);
    cudaGetSymbolAddress((void**)&pz,  g_z);
    cudaGetSymbolAddress((void**)&pwh, g_wthi);
    cudaGetSymbolAddress((void**)&pwl, g_wtlo);
    cudaGetSymbolAddress((void**)&pb,  g_bpack);

    cudaFuncSetAttribute(gemm_mma_kernel, cudaFuncAttributeMaxDynamicSharedMemorySize, SMEM_REQ);

    const int nvec = N_NODES * (D / 4);
    const int vblocks = (nvec + 255) / 256;
    const int nodeb = (N_NODES + 255) / 256;      // 391
    const int edgeb = (N_EDGES + 255) / 256;      // 6250
    const int mtiles = (N_NODES + 127) / 128;     // 782

    detect_kernel<<<1, 32>>>((const long long*)ei);
    zero_deg_kernel<<<nodeb, 256>>>();
    count_deg_kernel<<<edgeb, 256>>>(ei);
    scan1_kernel<<<nodeb, 256>>>();
    scan2_kernel<<<1, 512>>>(nodeb);
    rowptr_kernel<<<nodeb, 256>>>();
    scatter_kernel<<<edgeb, 256>>>(ei);
    copy_x_kernel<<<vblocks, 256>>>((const float4*)x_in);
    wpack_kernel<<<(N_LAYERS * DZ * D + 255) / 256, 256>>>(W_lin, W_film, W_skip, W_fskip);
    bpack_kernel<<<(N_LAYERS * DZ + 255) / 256, 256>>>(b_film);

    for (int l = 0; l < N_LAYERS; l++) {
        gemm_mma_kernel<<<dim3(DZ / 128, mtiles), 256, SMEM_REQ>>>(
            px, pwh + (size_t)l * DZ * D, pwl + (size_t)l * DZ * D,
            pb + (size_t)l * DZ, pz);
        float* dstp = (l == N_LAYERS - 1) ? out : px;
        node_kernel<<<(N_NODES + 7) / 8, 256>>>(dstp, l < N_LAYERS - 1 ? 1 : 0);
    }
}

// round 8
// speedup vs baseline: 2.4060x; 1.0053x over previous
#include <cuda_runtime.h>
#include <cuda_bf16.h>
#include <cstdint>

#define N_NODES 100000
#define N_EDGES 1600000
#define D       128
#define DZ      768          // fused output width: skip|beta_s|gamma_s|h|beta|gamma
#define N_LAYERS 4

// ---------------- scratch (device globals: no allocation allowed) ----------------
__device__ float g_x    [(size_t)N_NODES * D];
__device__ float g_z    [(size_t)N_NODES * DZ];
__device__ __nv_bfloat16 g_wthi[(size_t)N_LAYERS * DZ * D];   // W^T hi  [l][n][k]
__device__ __nv_bfloat16 g_wtlo[(size_t)N_LAYERS * DZ * D];   // W^T lo
__device__ float g_bpack[(size_t)N_LAYERS * DZ];
__device__ float g_deginv[N_NODES];
__device__ int   g_deg   [N_NODES];
__device__ int   g_scan  [N_NODES];
__device__ int   g_bsum  [512];
__device__ int   g_rowptr[N_NODES + 1];
__device__ int   g_fill  [N_NODES];
__device__ int   g_esrc  [N_EDGES];
__device__ int   g_is64;

// ---------------- PTX helpers ----------------
__device__ __forceinline__ uint32_t smem_u32(const void* p) {
    uint32_t a;
    asm("{ .reg .u64 t; cvta.to.shared.u64 t, %1; cvt.u32.u64 %0, t; }" : "=r"(a) : "l"(p));
    return a;
}
__device__ __forceinline__ void ldsm_x4(uint32_t addr, uint32_t* r) {
    asm volatile("ldmatrix.sync.aligned.m8n8.x4.shared.b16 {%0,%1,%2,%3}, [%4];"
                 : "=r"(r[0]), "=r"(r[1]), "=r"(r[2]), "=r"(r[3]) : "r"(addr));
}
__device__ __forceinline__ void mma_bf16(float* c, const uint32_t* a, const uint32_t* b) {
    asm volatile(
        "mma.sync.aligned.m16n8k16.row.col.f32.bf16.bf16.f32 "
        "{%0,%1,%2,%3}, {%4,%5,%6,%7}, {%8,%9}, {%0,%1,%2,%3};"
        : "+f"(c[0]), "+f"(c[1]), "+f"(c[2]), "+f"(c[3])
        : "r"(a[0]), "r"(a[1]), "r"(a[2]), "r"(a[3]), "r"(b[0]), "r"(b[1]));
}

// ---------------- edge-index dtype probe ----------------
__global__ void detect_kernel(const long long* __restrict__ ei) {
    if (threadIdx.x == 0 && blockIdx.x == 0) {
        int ok = 1;
        #pragma unroll
        for (int i = 0; i < 16; i++) {
            long long v = ei[i];
            if (v < 0 || v >= N_NODES) ok = 0;
        }
        g_is64 = ok;
    }
}
__device__ __forceinline__ int edge_at(const void* ei, size_t idx, int is64) {
    return is64 ? (int)((const long long*)ei)[idx] : ((const int*)ei)[idx];
}

// ---------------- degree + CSR build ----------------
__global__ void zero_deg_kernel() {
    int i = blockIdx.x * blockDim.x + threadIdx.x;
    if (i < N_NODES) g_deg[i] = 0;
}
__global__ void count_deg_kernel(const void* __restrict__ ei) {
    int e = blockIdx.x * blockDim.x + threadIdx.x;
    if (e < N_EDGES) atomicAdd(&g_deg[edge_at(ei, (size_t)N_EDGES + e, g_is64)], 1);
}
__global__ void scan1_kernel() {
    __shared__ int s[256];
    int tid = threadIdx.x, i = blockIdx.x * 256 + tid;
    int v = (i < N_NODES) ? g_deg[i] : 0;
    s[tid] = v; __syncthreads();
    #pragma unroll
    for (int off = 1; off < 256; off <<= 1) {
        int t = (tid >= off) ? s[tid - off] : 0;
        __syncthreads(); s[tid] += t; __syncthreads();
    }
    if (i < N_NODES) g_scan[i] = s[tid];
    if (tid == 255) g_bsum[blockIdx.x] = s[255];
}
__global__ void scan2_kernel(int nblk) {
    __shared__ int s[512];
    int tid = threadIdx.x;
    s[tid] = (tid < nblk) ? g_bsum[tid] : 0; __syncthreads();
    #pragma unroll
    for (int off = 1; off < 512; off <<= 1) {
        int t = (tid >= off) ? s[tid - off] : 0;
        __syncthreads(); s[tid] += t; __syncthreads();
    }
    if (tid < nblk) g_bsum[tid] = s[tid];
}
__global__ void rowptr_kernel() {
    int i = blockIdx.x * blockDim.x + threadIdx.x;
    if (i < N_NODES) {
        int blk = i >> 8;
        int off = (blk > 0) ? g_bsum[blk - 1] : 0;
        g_rowptr[i] = g_scan[i] - g_deg[i] + off;
        g_fill[i] = 0;
        g_deginv[i] = 1.0f / fmaxf((float)g_deg[i], 1.0f);
    }
    if (i == 0) g_rowptr[N_NODES] = N_EDGES;
}
__global__ void scatter_kernel(const void* __restrict__ ei) {
    int e = blockIdx.x * blockDim.x + threadIdx.x;
    if (e < N_EDGES) {
        int is64 = g_is64;
        int s = edge_at(ei, (size_t)e, is64);
        int d = edge_at(ei, (size_t)N_EDGES + e, is64);
        g_esrc[g_rowptr[d] + atomicAdd(&g_fill[d], 1)] = s;
    }
}
__global__ void copy_x_kernel(const float4* __restrict__ src) {
    int i = blockIdx.x * blockDim.x + threadIdx.x;
    if (i < N_NODES * (D / 4)) ((float4*)g_x)[i] = src[i];
}

// ---------------- weight packing: W^T hi/lo bf16 split -------------------------
// fused cols: [0,128)=W_skip [128,384)=W_fskip [384,512)=W_lin [512,768)=W_film
__global__ void wpack_kernel(const float* __restrict__ W_lin,
                             const float* __restrict__ W_film,
                             const float* __restrict__ W_skip,
                             const float* __restrict__ W_fskip) {
    int i = blockIdx.x * blockDim.x + threadIdx.x;   // [0, 4*768*128)
    if (i >= N_LAYERS * DZ * D) return;
    int k = i % D;
    int n = (i / D) % DZ;
    int l = i / (D * DZ);
    float v;
    if (n < 128)      v = W_skip [((size_t)l * D + k) * 128 + n];
    else if (n < 384) v = W_fskip[((size_t)l * D + k) * 256 + (n - 128)];
    else if (n < 512) v = W_lin  [((size_t)l * D + k) * 128 + (n - 384)];
    else              v = W_film [((size_t)l * D + k) * 256 + (n - 512)];
    __nv_bfloat16 hi = __float2bfloat16_rn(v);
    __nv_bfloat16 lo = __float2bfloat16_rn(v - __bfloat162float(hi));
    g_wthi[i] = hi;
    g_wtlo[i] = lo;
}
__global__ void bpack_kernel(const float* __restrict__ b_film) {
    int i = blockIdx.x * blockDim.x + threadIdx.x;
    if (i >= N_LAYERS * DZ) return;
    int c = i % DZ, l = i / DZ;
    g_bpack[i] = (c >= 512) ? b_film[(size_t)l * 256 + (c - 512)] : 0.0f;
}

// ---------------- mma.sync bf16 GEMM: z tile [128x128] = A @ W^T + bias --------
// 3 passes: Ahi*Bhi + Ahi*Blo + Alo*Bhi, fp32 accum. K=128 smem-resident.
// Smem rows: 128 k-elems bf16 = 256B = 16 chunks of 16B; chunk swizzle ^ (row&7).
#define OFF_AHI  0
#define OFF_ALO  32768
#define OFF_BHI  65536
#define OFF_BLO  98304
#define SMEM_REQ 131072

__global__ __launch_bounds__(256, 1)
void gemm_mma_kernel(const float* __restrict__ A,
                     const __nv_bfloat16* __restrict__ Bhi,
                     const __nv_bfloat16* __restrict__ Blo,
                     const float* __restrict__ bias, float* __restrict__ C) {
    extern __shared__ char sm[];
    uint32_t sb = smem_u32(sm);
    int tid = threadIdx.x, wid = tid >> 5, lane = tid & 31;
    int row0 = blockIdx.y * 128;
    int n0   = blockIdx.x * 128;

    // ---- A loader: split fp32 -> bf16 hi/lo. thread = (row=tid/2, half=tid&1)
    {
        int r = tid >> 1, h = tid & 1;
        int grow = row0 + r;
        uint32_t rbase = r * 256;
        int r7 = r & 7;
        if (grow < N_NODES) {
            const float4* ap = (const float4*)(A + (size_t)grow * D + h * 64);
            #pragma unroll
            for (int it = 0; it < 8; it++) {
                float4 f0 = ap[it * 2], f1 = ap[it * 2 + 1];
                float f[8] = {f0.x, f0.y, f0.z, f0.w, f1.x, f1.y, f1.z, f1.w};
                __nv_bfloat16 hi8[8], lo8[8];
                #pragma unroll
                for (int q = 0; q < 8; q++) {
                    hi8[q] = __float2bfloat16_rn(f[q]);
                    lo8[q] = __float2bfloat16_rn(f[q] - __bfloat162float(hi8[q]));
                }
                int kc = h * 8 + it;
                uint32_t off = rbase + (uint32_t)((kc ^ r7) << 4);
                *(uint4*)(sm + OFF_AHI + off) = *(const uint4*)hi8;
                *(uint4*)(sm + OFF_ALO + off) = *(const uint4*)lo8;
            }
        } else {
            uint4 z = make_uint4(0, 0, 0, 0);
            #pragma unroll
            for (int it = 0; it < 8; it++) {
                int kc = h * 8 + it;
                uint32_t off = rbase + (uint32_t)((kc ^ r7) << 4);
                *(uint4*)(sm + OFF_AHI + off) = z;
                *(uint4*)(sm + OFF_ALO + off) = z;
            }
        }
    }
    // ---- B loader: copy prepacked bf16 hi/lo rows n0..n0+127
    {
        int n = tid >> 1, h = tid & 1;
        const uint4* bh = (const uint4*)(Bhi + (size_t)(n0 + n) * D + h * 64);
        const uint4* bl = (const uint4*)(Blo + (size_t)(n0 + n) * D + h * 64);
        uint32_t nb = n * 256;
        int n7 = n & 7;
        #pragma unroll
        for (int it = 0; it < 8; it++) {
            int kc = h * 8 + it;
            uint32_t off = nb + (uint32_t)((kc ^ n7) << 4);
            *(uint4*)(sm + OFF_BHI + off) = bh[it];
            *(uint4*)(sm + OFF_BLO + off) = bl[it];
        }
    }
    __syncthreads();

    // warp grid: 4 (M) x 2 (N); warp tile 32 rows x 64 cols
    int warpM = wid & 3, warpN = wid >> 2;
    float acc[2][8][4];
    #pragma unroll
    for (int mt = 0; mt < 2; mt++)
        #pragma unroll
        for (int nt = 0; nt < 8; nt++)
            #pragma unroll
            for (int q = 0; q < 4; q++) acc[mt][nt][q] = 0.0f;

    const int laneA_m   = lane & 15;
    const int laneA_kad = lane >> 4;                       // 0/1
    const int laneB_n   = (lane & 7) + ((lane & 16) ? 8 : 0);
    const int laneB_kad = (lane >> 3) & 1;

    #pragma unroll 1
    for (int pass = 0; pass < 3; pass++) {
        uint32_t abase = sb + (pass == 2 ? OFF_ALO : OFF_AHI);
        uint32_t bbase = sb + (pass == 1 ? OFF_BLO : OFF_BHI);
        #pragma unroll
        for (int ks = 0; ks < 8; ks++) {
            uint32_t af[2][4];
            #pragma unroll
            for (int mt = 0; mt < 2; mt++) {
                int m = warpM * 32 + mt * 16 + laneA_m;
                int kc = ks * 2 + laneA_kad;
                uint32_t ad = abase + m * 256 + (uint32_t)(((kc ^ (m & 7))) << 4);
                ldsm_x4(ad, af[mt]);
            }
            uint32_t bfr[8][2];
            #pragma unroll
            for (int g = 0; g < 4; g++) {
                int n = warpN * 64 + g * 16 + laneB_n;
                int kc = ks * 2 + laneB_kad;
                uint32_t bd = bbase + n * 256 + (uint32_t)(((kc ^ (n & 7))) << 4);
                uint32_t r[4];
                ldsm_x4(bd, r);
                bfr[g * 2][0] = r[0]; bfr[g * 2][1] = r[1];
                bfr[g * 2 + 1][0] = r[2]; bfr[g * 2 + 1][1] = r[3];
            }
            #pragma unroll
            for (int mt = 0; mt < 2; mt++)
                #pragma unroll
                for (int nt = 0; nt < 8; nt++)
                    mma_bf16(acc[mt][nt], af[mt], bfr[nt]);
        }
    }

    // ---- epilogue: c0,c1 -> (row, col..col+1); c2,c3 -> (row+8)
    int rbase = row0 + warpM * 32 + (lane >> 2);
    int cbase = n0 + warpN * 64 + (lane & 3) * 2;
    #pragma unroll
    for (int mt = 0; mt < 2; mt++) {
        #pragma unroll
        for (int nt = 0; nt < 8; nt++) {
            int col = cbase + nt * 8;
            float b0 = bias[col], b1 = bias[col + 1];
            int r1 = rbase + mt * 16;
            if (r1 < N_NODES) {
                float2 v = make_float2(acc[mt][nt][0] + b0, acc[mt][nt][1] + b1);
                *(float2*)(C + (size_t)r1 * DZ + col) = v;
            }
            int r2 = r1 + 8;
            if (r2 < N_NODES) {
                float2 v = make_float2(acc[mt][nt][2] + b0, acc[mt][nt][3] + b1);
                *(float2*)(C + (size_t)r2 * DZ + col) = v;
            }
        }
    }
}

// ---------------- fused node kernel: self-FiLM + CSR aggregation + finalize -----
// One warp per node; 4-way edge unroll for MLP. z row (float4 units, 192/row):
// skip@0 beta_s@32 gamma_s@64 h@96 beta@128 gamma@160.
__global__ __launch_bounds__(256)
void node_kernel(float* __restrict__ dstp, int do_relu) {
    int n = blockIdx.x * 8 + (threadIdx.x >> 5);
    if (n >= N_NODES) return;
    int lane = threadIdx.x & 31;
    const float4* z4 = (const float4*)g_z;
    size_t rb = (size_t)n * 192;

    float4 skip = z4[rb + lane];
    float4 bs   = z4[rb + 32 + lane];
    float4 gs   = z4[rb + 64 + lane];
    float4 be   = z4[rb + 128 + lane];
    float4 ga   = z4[rb + 160 + lane];

    float4 acc = make_float4(0.f, 0.f, 0.f, 0.f);
    int e  = g_rowptr[n];
    int e1 = g_rowptr[n + 1];
    for (; e + 3 < e1; e += 4) {
        int s0 = g_esrc[e];
        int s1 = g_esrc[e + 1];
        int s2 = g_esrc[e + 2];
        int s3 = g_esrc[e + 3];
        float4 h0 = z4[(size_t)s0 * 192 + 96 + lane];
        float4 h1 = z4[(size_t)s1 * 192 + 96 + lane];
        float4 h2 = z4[(size_t)s2 * 192 + 96 + lane];
        float4 h3 = z4[(size_t)s3 * 192 + 96 + lane];
        acc.x += fmaxf(fmaf(ga.x, h0.x, be.x), 0.f) + fmaxf(fmaf(ga.x, h1.x, be.x), 0.f)
               + fmaxf(fmaf(ga.x, h2.x, be.x), 0.f) + fmaxf(fmaf(ga.x, h3.x, be.x), 0.f);
        acc.y += fmaxf(fmaf(ga.y, h0.y, be.y), 0.f) + fmaxf(fmaf(ga.y, h1.y, be.y), 0.f)
               + fmaxf(fmaf(ga.y, h2.y, be.y), 0.f) + fmaxf(fmaf(ga.y, h3.y, be.y), 0.f);
        acc.z += fmaxf(fmaf(ga.z, h0.z, be.z), 0.f) + fmaxf(fmaf(ga.z, h1.z, be.z), 0.f)
               + fmaxf(fmaf(ga.z, h2.z, be.z), 0.f) + fmaxf(fmaf(ga.z, h3.z, be.z), 0.f);
        acc.w += fmaxf(fmaf(ga.w, h0.w, be.w), 0.f) + fmaxf(fmaf(ga.w, h1.w, be.w), 0.f)
               + fmaxf(fmaf(ga.w, h2.w, be.w), 0.f) + fmaxf(fmaf(ga.w, h3.w, be.w), 0.f);
    }
    for (; e < e1; e++) {
        int s0 = g_esrc[e];
        float4 h0 = z4[(size_t)s0 * 192 + 96 + lane];
        acc.x += fmaxf(fmaf(ga.x, h0.x, be.x), 0.f);
        acc.y += fmaxf(fmaf(ga.y, h0.y, be.y), 0.f);
        acc.z += fmaxf(fmaf(ga.z, h0.z, be.z), 0.f);
        acc.w += fmaxf(fmaf(ga.w, h0.w, be.w), 0.f);
    }

    float di = g_deginv[n];
    float4 o;
    o.x = fmaxf(fmaf(gs.x, skip.x, bs.x), 0.f) + acc.x * di;
    o.y = fmaxf(fmaf(gs.y, skip.y, bs.y), 0.f) + acc.y * di;
    o.z = fmaxf(fmaf(gs.z, skip.z, bs.z), 0.f) + acc.z * di;
    o.w = fmaxf(fmaf(gs.w, skip.w, bs.w), 0.f) + acc.w * di;
    if (do_relu) {
        o.x = fmaxf(o.x, 0.f); o.y = fmaxf(o.y, 0.f);
        o.z = fmaxf(o.z, 0.f); o.w = fmaxf(o.w, 0.f);
    }
    ((float4*)dstp)[(size_t)n * 32 + lane] = o;
}

// ---------------- launch --------------------------------------------------------
// Launch order puts the first gemm_mma_kernel at index 5 so ncu (-s 5 -c 1)
// profiles the dominant kernel instead of a CSR-build helper. Dependencies:
// gemm needs detect/copy_x/wpack/bpack only; CSR build must precede node_kernel.
extern "C" void kernel_launch(void* const* d_in, const int* in_sizes, int n_in,
                              void* d_out, int out_size) {
    const float* x_in    = (const float*)d_in[0];
    const void*  ei      = d_in[1];
    const float* W_lin   = (const float*)d_in[2];
    const float* W_film  = (const float*)d_in[3];
    const float* b_film  = (const float*)d_in[4];
    const float* W_skip  = (const float*)d_in[5];
    const float* W_fskip = (const float*)d_in[6];
    float*       out     = (float*)d_out;

    float *px, *pz, *pb;
    __nv_bfloat16 *pwh, *pwl;
    cudaGetSymbolAddress((void**)&px,  g_x);
    cudaGetSymbolAddress((void**)&pz,  g_z);
    cudaGetSymbolAddress((void**)&pwh, g_wthi);
    cudaGetSymbolAddress((void**)&pwl, g_wtlo);
    cudaGetSymbolAddress((void**)&pb,  g_bpack);

    cudaFuncSetAttribute(gemm_mma_kernel, cudaFuncAttributeMaxDynamicSharedMemorySize, SMEM_REQ);

    const int nvec = N_NODES * (D / 4);
    const int vblocks = (nvec + 255) / 256;
    const int nodeb = (N_NODES + 255) / 256;      // 391
    const int edgeb = (N_EDGES + 255) / 256;      // 6250
    const int mtiles = (N_NODES + 127) / 128;     // 782

    // 0-4: prerequisites of the first GEMM
    detect_kernel<<<1, 32>>>((const long long*)ei);                                      // 0
    copy_x_kernel<<<vblocks, 256>>>((const float4*)x_in);                                // 1
    wpack_kernel<<<(N_LAYERS * DZ * D + 255) / 256, 256>>>(W_lin, W_film, W_skip, W_fskip); // 2
    bpack_kernel<<<(N_LAYERS * DZ + 255) / 256, 256>>>(b_film);                          // 3
    zero_deg_kernel<<<nodeb, 256>>>();                                                   // 4

    // 5: first-layer GEMM (profiled by ncu -s 5 -c 1)
    gemm_mma_kernel<<<dim3(DZ / 128, mtiles), 256, SMEM_REQ>>>(
        px, pwh, pwl, pb, pz);                                                           // 5

    // 6-10: CSR build (must complete before first node_kernel)
    count_deg_kernel<<<edgeb, 256>>>(ei);                                                // 6
    scan1_kernel<<<nodeb, 256>>>();                                                      // 7
    scan2_kernel<<<1, 512>>>(nodeb);                                                     // 8
    rowptr_kernel<<<nodeb, 256>>>();                                                     // 9
    scatter_kernel<<<edgeb, 256>>>(ei);                                                  // 10

    for (int l = 0; l < N_LAYERS; l++) {
        if (l > 0) {
            gemm_mma_kernel<<<dim3(DZ / 128, mtiles), 256, SMEM_REQ>>>(
                px, pwh + (size_t)l * DZ * D, pwl + (size_t)l * DZ * D,
                pb + (size_t)l * DZ, pz);
        }
        float* dstp = (l == N_LAYERS - 1) ? out : px;
        node_kernel<<<(N_NODES + 7) / 8, 256>>>(dstp, l < N_LAYERS - 1 ? 1 : 0);
    }
}

// round 9
// speedup vs baseline: 2.6499x; 1.1014x over previous
#include <cuda_runtime.h>
#include <cuda_bf16.h>
#include <cstdint>

#define N_NODES 100000
#define N_EDGES 1600000
#define D       128
#define DZ      768          // fused output width: skip|beta_s|gamma_s|h|beta|gamma
#define N_LAYERS 4

// ---------------- scratch (device globals: no allocation allowed) ----------------
__device__ float g_x    [(size_t)N_NODES * D];
__device__ float g_z    [(size_t)N_NODES * DZ];
__device__ __nv_bfloat16 g_wthi[(size_t)N_LAYERS * DZ * D];   // W^T hi  [l][n][k]
__device__ __nv_bfloat16 g_wtlo[(size_t)N_LAYERS * DZ * D];   // W^T lo
__device__ float g_bpack[(size_t)N_LAYERS * DZ];
__device__ float g_deginv[N_NODES];
__device__ int   g_deg   [N_NODES];
__device__ int   g_scan  [N_NODES];
__device__ int   g_bsum  [512];
__device__ int   g_rowptr[N_NODES + 1];
__device__ int   g_fill  [N_NODES];
__device__ int   g_esrc  [N_EDGES];
__device__ int   g_is64;

// ---------------- PTX helpers ----------------
__device__ __forceinline__ uint32_t smem_u32(const void* p) {
    uint32_t a;
    asm("{ .reg .u64 t; cvta.to.shared.u64 t, %1; cvt.u32.u64 %0, t; }" : "=r"(a) : "l"(p));
    return a;
}
__device__ __forceinline__ void ldsm_x4(uint32_t addr, uint32_t* r) {
    asm volatile("ldmatrix.sync.aligned.m8n8.x4.shared.b16 {%0,%1,%2,%3}, [%4];"
                 : "=r"(r[0]), "=r"(r[1]), "=r"(r[2]), "=r"(r[3]) : "r"(addr));
}
__device__ __forceinline__ void mma_bf16(float* c, const uint32_t* a, const uint32_t* b) {
    asm volatile(
        "mma.sync.aligned.m16n8k16.row.col.f32.bf16.bf16.f32 "
        "{%0,%1,%2,%3}, {%4,%5,%6,%7}, {%8,%9}, {%0,%1,%2,%3};"
        : "+f"(c[0]), "+f"(c[1]), "+f"(c[2]), "+f"(c[3])
        : "r"(a[0]), "r"(a[1]), "r"(a[2]), "r"(a[3]), "r"(b[0]), "r"(b[1]));
}

// ---------------- edge-index dtype probe ----------------
__global__ void detect_kernel(const long long* __restrict__ ei) {
    if (threadIdx.x == 0 && blockIdx.x == 0) {
        int ok = 1;
        #pragma unroll
        for (int i = 0; i < 16; i++) {
            long long v = ei[i];
            if (v < 0 || v >= N_NODES) ok = 0;
        }
        g_is64 = ok;
    }
}
__device__ __forceinline__ int edge_at(const void* ei, size_t idx, int is64) {
    return is64 ? (int)((const long long*)ei)[idx] : ((const int*)ei)[idx];
}

// ---------------- degree + CSR build ----------------
__global__ void zero_deg_kernel() {
    int i = blockIdx.x * blockDim.x + threadIdx.x;
    if (i < N_NODES) g_deg[i] = 0;
}
__global__ void count_deg_kernel(const void* __restrict__ ei) {
    int e = blockIdx.x * blockDim.x + threadIdx.x;
    if (e < N_EDGES) atomicAdd(&g_deg[edge_at(ei, (size_t)N_EDGES + e, g_is64)], 1);
}
__global__ void scan1_kernel() {
    __shared__ int s[256];
    int tid = threadIdx.x, i = blockIdx.x * 256 + tid;
    int v = (i < N_NODES) ? g_deg[i] : 0;
    s[tid] = v; __syncthreads();
    #pragma unroll
    for (int off = 1; off < 256; off <<= 1) {
        int t = (tid >= off) ? s[tid - off] : 0;
        __syncthreads(); s[tid] += t; __syncthreads();
    }
    if (i < N_NODES) g_scan[i] = s[tid];
    if (tid == 255) g_bsum[blockIdx.x] = s[255];
}
__global__ void scan2_kernel(int nblk) {
    __shared__ int s[512];
    int tid = threadIdx.x;
    s[tid] = (tid < nblk) ? g_bsum[tid] : 0; __syncthreads();
    #pragma unroll
    for (int off = 1; off < 512; off <<= 1) {
        int t = (tid >= off) ? s[tid - off] : 0;
        __syncthreads(); s[tid] += t; __syncthreads();
    }
    if (tid < nblk) g_bsum[tid] = s[tid];
}
__global__ void rowptr_kernel() {
    int i = blockIdx.x * blockDim.x + threadIdx.x;
    if (i < N_NODES) {
        int blk = i >> 8;
        int off = (blk > 0) ? g_bsum[blk - 1] : 0;
        g_rowptr[i] = g_scan[i] - g_deg[i] + off;
        g_fill[i] = 0;
        g_deginv[i] = 1.0f / fmaxf((float)g_deg[i], 1.0f);
    }
    if (i == 0) g_rowptr[N_NODES] = N_EDGES;
}
__global__ void scatter_kernel(const void* __restrict__ ei) {
    int e = blockIdx.x * blockDim.x + threadIdx.x;
    if (e < N_EDGES) {
        int is64 = g_is64;
        int s = edge_at(ei, (size_t)e, is64);
        int d = edge_at(ei, (size_t)N_EDGES + e, is64);
        g_esrc[g_rowptr[d] + atomicAdd(&g_fill[d], 1)] = s;
    }
}
__global__ void copy_x_kernel(const float4* __restrict__ src) {
    int i = blockIdx.x * blockDim.x + threadIdx.x;
    if (i < N_NODES * (D / 4)) ((float4*)g_x)[i] = src[i];
}

// ---------------- weight packing: W^T hi/lo bf16 split -------------------------
// fused cols: [0,128)=W_skip [128,384)=W_fskip [384,512)=W_lin [512,768)=W_film
__global__ void wpack_kernel(const float* __restrict__ W_lin,
                             const float* __restrict__ W_film,
                             const float* __restrict__ W_skip,
                             const float* __restrict__ W_fskip) {
    int i = blockIdx.x * blockDim.x + threadIdx.x;   // [0, 4*768*128)
    if (i >= N_LAYERS * DZ * D) return;
    int k = i % D;
    int n = (i / D) % DZ;
    int l = i / (D * DZ);
    float v;
    if (n < 128)      v = W_skip [((size_t)l * D + k) * 128 + n];
    else if (n < 384) v = W_fskip[((size_t)l * D + k) * 256 + (n - 128)];
    else if (n < 512) v = W_lin  [((size_t)l * D + k) * 128 + (n - 384)];
    else              v = W_film [((size_t)l * D + k) * 256 + (n - 512)];
    __nv_bfloat16 hi = __float2bfloat16_rn(v);
    __nv_bfloat16 lo = __float2bfloat16_rn(v - __bfloat162float(hi));
    g_wthi[i] = hi;
    g_wtlo[i] = lo;
}
__global__ void bpack_kernel(const float* __restrict__ b_film) {
    int i = blockIdx.x * blockDim.x + threadIdx.x;
    if (i >= N_LAYERS * DZ) return;
    int c = i % DZ, l = i / DZ;
    g_bpack[i] = (c >= 512) ? b_film[(size_t)l * 256 + (c - 512)] : 0.0f;
}

// ---------------- mma.sync bf16 GEMM, persistent over the 6 column tiles -------
// One CTA per 128-row tile; A loaded+split ONCE, then loop nt=0..5 over B tiles.
// 3 passes per tile: Ahi*Bhi + Ahi*Blo + Alo*Bhi, fp32 accum. K=128 smem-resident.
// Smem rows: 128 k-elems bf16 = 256B = 16 chunks of 16B; chunk swizzle ^ (row&7).
#define OFF_AHI  0
#define OFF_ALO  32768
#define OFF_BHI  65536
#define OFF_BLO  98304
#define SMEM_REQ 131072
#define NTILES   (DZ / 128)   // 6

__global__ __launch_bounds__(256, 1)
void gemm_mma_kernel(const float* __restrict__ A,
                     const __nv_bfloat16* __restrict__ Bhi,
                     const __nv_bfloat16* __restrict__ Blo,
                     const float* __restrict__ bias, float* __restrict__ C) {
    extern __shared__ char sm[];
    uint32_t sb = smem_u32(sm);
    int tid = threadIdx.x, wid = tid >> 5, lane = tid & 31;
    int row0 = blockIdx.x * 128;

    // ---- A loader (once): split fp32 -> bf16 hi/lo. thread = (row=tid/2, half=tid&1)
    {
        int r = tid >> 1, h = tid & 1;
        int grow = row0 + r;
        uint32_t rbase = r * 256;
        int r7 = r & 7;
        if (grow < N_NODES) {
            const float4* ap = (const float4*)(A + (size_t)grow * D + h * 64);
            #pragma unroll
            for (int it = 0; it < 8; it++) {
                float4 f0 = ap[it * 2], f1 = ap[it * 2 + 1];
                float f[8] = {f0.x, f0.y, f0.z, f0.w, f1.x, f1.y, f1.z, f1.w};
                __nv_bfloat16 hi8[8], lo8[8];
                #pragma unroll
                for (int q = 0; q < 8; q++) {
                    hi8[q] = __float2bfloat16_rn(f[q]);
                    lo8[q] = __float2bfloat16_rn(f[q] - __bfloat162float(hi8[q]));
                }
                int kc = h * 8 + it;
                uint32_t off = rbase + (uint32_t)((kc ^ r7) << 4);
                *(uint4*)(sm + OFF_AHI + off) = *(const uint4*)hi8;
                *(uint4*)(sm + OFF_ALO + off) = *(const uint4*)lo8;
            }
        } else {
            uint4 z = make_uint4(0, 0, 0, 0);
            #pragma unroll
            for (int it = 0; it < 8; it++) {
                int kc = h * 8 + it;
                uint32_t off = rbase + (uint32_t)((kc ^ r7) << 4);
                *(uint4*)(sm + OFF_AHI + off) = z;
                *(uint4*)(sm + OFF_ALO + off) = z;
            }
        }
    }

    // warp grid: 4 (M) x 2 (N); warp tile 32 rows x 64 cols
    const int warpM = wid & 3, warpN = wid >> 2;
    const int laneA_m   = lane & 15;
    const int laneA_kad = lane >> 4;                       // 0/1
    const int laneB_n   = (lane & 7) + ((lane & 16) ? 8 : 0);
    const int laneB_kad = (lane >> 3) & 1;

    const int bld_n = tid >> 1, bld_h = tid & 1;           // B loader mapping
    const uint32_t bld_nb = bld_n * 256;
    const int bld_n7 = bld_n & 7;

    #pragma unroll 1
    for (int nt = 0; nt < NTILES; nt++) {
        const int n0 = nt * 128;

        // ---- load B tile nt (prepacked bf16 hi/lo rows n0..n0+127)
        {
            const uint4* bh = (const uint4*)(Bhi + (size_t)(n0 + bld_n) * D + bld_h * 64);
            const uint4* bl = (const uint4*)(Blo + (size_t)(n0 + bld_n) * D + bld_h * 64);
            #pragma unroll
            for (int it = 0; it < 8; it++) {
                int kc = bld_h * 8 + it;
                uint32_t off = bld_nb + (uint32_t)((kc ^ bld_n7) << 4);
                *(uint4*)(sm + OFF_BHI + off) = bh[it];
                *(uint4*)(sm + OFF_BLO + off) = bl[it];
            }
        }
        __syncthreads();

        float acc[2][8][4];
        #pragma unroll
        for (int mt = 0; mt < 2; mt++)
            #pragma unroll
            for (int ntt = 0; ntt < 8; ntt++)
                #pragma unroll
                for (int q = 0; q < 4; q++) acc[mt][ntt][q] = 0.0f;

        #pragma unroll 1
        for (int pass = 0; pass < 3; pass++) {
            uint32_t abase = sb + (pass == 2 ? OFF_ALO : OFF_AHI);
            uint32_t bbase = sb + (pass == 1 ? OFF_BLO : OFF_BHI);
            #pragma unroll
            for (int ks = 0; ks < 8; ks++) {
                uint32_t af[2][4];
                #pragma unroll
                for (int mt = 0; mt < 2; mt++) {
                    int m = warpM * 32 + mt * 16 + laneA_m;
                    int kc = ks * 2 + laneA_kad;
                    uint32_t ad = abase + m * 256 + (uint32_t)(((kc ^ (m & 7))) << 4);
                    ldsm_x4(ad, af[mt]);
                }
                uint32_t bfr[8][2];
                #pragma unroll
                for (int g = 0; g < 4; g++) {
                    int n = warpN * 64 + g * 16 + laneB_n;
                    int kc = ks * 2 + laneB_kad;
                    uint32_t bd = bbase + n * 256 + (uint32_t)(((kc ^ (n & 7))) << 4);
                    uint32_t r[4];
                    ldsm_x4(bd, r);
                    bfr[g * 2][0] = r[0]; bfr[g * 2][1] = r[1];
                    bfr[g * 2 + 1][0] = r[2]; bfr[g * 2 + 1][1] = r[3];
                }
                #pragma unroll
                for (int mt = 0; mt < 2; mt++)
                    #pragma unroll
                    for (int ntt = 0; ntt < 8; ntt++)
                        mma_bf16(acc[mt][ntt], af[mt], bfr[ntt]);
            }
        }

        // ---- epilogue: c0,c1 -> (row, col..col+1); c2,c3 -> (row+8)
        int rbase = row0 + warpM * 32 + (lane >> 2);
        int cbase = n0 + warpN * 64 + (lane & 3) * 2;
        #pragma unroll
        for (int mt = 0; mt < 2; mt++) {
            #pragma unroll
            for (int ntt = 0; ntt < 8; ntt++) {
                int col = cbase + ntt * 8;
                float b0 = bias[col], b1 = bias[col + 1];
                int r1 = rbase + mt * 16;
                if (r1 < N_NODES) {
                    float2 v = make_float2(acc[mt][ntt][0] + b0, acc[mt][ntt][1] + b1);
                    *(float2*)(C + (size_t)r1 * DZ + col) = v;
                }
                int r2 = r1 + 8;
                if (r2 < N_NODES) {
                    float2 v = make_float2(acc[mt][ntt][2] + b0, acc[mt][ntt][3] + b1);
                    *(float2*)(C + (size_t)r2 * DZ + col) = v;
                }
            }
        }
        __syncthreads();   // B buffer reused next iteration
    }
}

// ---------------- fused node kernel: self-FiLM + CSR aggregation + finalize -----
// One warp per node; 4-way edge unroll. z row (float4 units, 192/row):
// skip@0 beta_s@32 gamma_s@64 h@96 beta@128 gamma@160.
__global__ __launch_bounds__(256)
void node_kernel(float* __restrict__ dstp, int do_relu) {
    int n = blockIdx.x * 8 + (threadIdx.x >> 5);
    if (n >= N_NODES) return;
    int lane = threadIdx.x & 31;
    const float4* z4 = (const float4*)g_z;
    size_t rb = (size_t)n * 192;

    float4 skip = z4[rb + lane];
    float4 bs   = z4[rb + 32 + lane];
    float4 gs   = z4[rb + 64 + lane];
    float4 be   = z4[rb + 128 + lane];
    float4 ga   = z4[rb + 160 + lane];

    float4 acc = make_float4(0.f, 0.f, 0.f, 0.f);
    int e  = g_rowptr[n];
    int e1 = g_rowptr[n + 1];
    for (; e + 3 < e1; e += 4) {
        int s0 = g_esrc[e];
        int s1 = g_esrc[e + 1];
        int s2 = g_esrc[e + 2];
        int s3 = g_esrc[e + 3];
        float4 h0 = z4[(size_t)s0 * 192 + 96 + lane];
        float4 h1 = z4[(size_t)s1 * 192 + 96 + lane];
        float4 h2 = z4[(size_t)s2 * 192 + 96 + lane];
        float4 h3 = z4[(size_t)s3 * 192 + 96 + lane];
        acc.x += fmaxf(fmaf(ga.x, h0.x, be.x), 0.f) + fmaxf(fmaf(ga.x, h1.x, be.x), 0.f)
               + fmaxf(fmaf(ga.x, h2.x, be.x), 0.f) + fmaxf(fmaf(ga.x, h3.x, be.x), 0.f);
        acc.y += fmaxf(fmaf(ga.y, h0.y, be.y), 0.f) + fmaxf(fmaf(ga.y, h1.y, be.y), 0.f)
               + fmaxf(fmaf(ga.y, h2.y, be.y), 0.f) + fmaxf(fmaf(ga.y, h3.y, be.y), 0.f);
        acc.z += fmaxf(fmaf(ga.z, h0.z, be.z), 0.f) + fmaxf(fmaf(ga.z, h1.z, be.z), 0.f)
               + fmaxf(fmaf(ga.z, h2.z, be.z), 0.f) + fmaxf(fmaf(ga.z, h3.z, be.z), 0.f);
        acc.w += fmaxf(fmaf(ga.w, h0.w, be.w), 0.f) + fmaxf(fmaf(ga.w, h1.w, be.w), 0.f)
               + fmaxf(fmaf(ga.w, h2.w, be.w), 0.f) + fmaxf(fmaf(ga.w, h3.w, be.w), 0.f);
    }
    for (; e < e1; e++) {
        int s0 = g_esrc[e];
        float4 h0 = z4[(size_t)s0 * 192 + 96 + lane];
        acc.x += fmaxf(fmaf(ga.x, h0.x, be.x), 0.f);
        acc.y += fmaxf(fmaf(ga.y, h0.y, be.y), 0.f);
        acc.z += fmaxf(fmaf(ga.z, h0.z, be.z), 0.f);
        acc.w += fmaxf(fmaf(ga.w, h0.w, be.w), 0.f);
    }

    float di = g_deginv[n];
    float4 o;
    o.x = fmaxf(fmaf(gs.x, skip.x, bs.x), 0.f) + acc.x * di;
    o.y = fmaxf(fmaf(gs.y, skip.y, bs.y), 0.f) + acc.y * di;
    o.z = fmaxf(fmaf(gs.z, skip.z, bs.z), 0.f) + acc.z * di;
    o.w = fmaxf(fmaf(gs.w, skip.w, bs.w), 0.f) + acc.w * di;
    if (do_relu) {
        o.x = fmaxf(o.x, 0.f); o.y = fmaxf(o.y, 0.f);
        o.z = fmaxf(o.z, 0.f); o.w = fmaxf(o.w, 0.f);
    }
    ((float4*)dstp)[(size_t)n * 32 + lane] = o;
}

// ---------------- launch --------------------------------------------------------
// Launch order: gemm at index 3 (ncu -s 5 was observed to land on index 3).
// gemm prereqs: copy_x, wpack, bpack. detect/CSR only needed before node_kernel.
extern "C" void kernel_launch(void* const* d_in, const int* in_sizes, int n_in,
                              void* d_out, int out_size) {
    const float* x_in    = (const float*)d_in[0];
    const void*  ei      = d_in[1];
    const float* W_lin   = (const float*)d_in[2];
    const float* W_film  = (const float*)d_in[3];
    const float* b_film  = (const float*)d_in[4];
    const float* W_skip  = (const float*)d_in[5];
    const float* W_fskip = (const float*)d_in[6];
    float*       out     = (float*)d_out;

    float *px, *pz, *pb;
    __nv_bfloat16 *pwh, *pwl;
    cudaGetSymbolAddress((void**)&px,  g_x);
    cudaGetSymbolAddress((void**)&pz,  g_z);
    cudaGetSymbolAddress((void**)&pwh, g_wthi);
    cudaGetSymbolAddress((void**)&pwl, g_wtlo);
    cudaGetSymbolAddress((void**)&pb,  g_bpack);

    cudaFuncSetAttribute(gemm_mma_kernel, cudaFuncAttributeMaxDynamicSharedMemorySize, SMEM_REQ);

    const int nvec = N_NODES * (D / 4);
    const int vblocks = (nvec + 255) / 256;
    const int nodeb = (N_NODES + 255) / 256;      // 391
    const int edgeb = (N_EDGES + 255) / 256;      // 6250
    const int mtiles = (N_NODES + 127) / 128;     // 782

    // 0-2: prerequisites of the first GEMM
    copy_x_kernel<<<vblocks, 256>>>((const float4*)x_in);                                // 0
    wpack_kernel<<<(N_LAYERS * DZ * D + 255) / 256, 256>>>(W_lin, W_film, W_skip, W_fskip); // 1
    bpack_kernel<<<(N_LAYERS * DZ + 255) / 256, 256>>>(b_film);                          // 2

    // 3: first-layer GEMM (target of ncu skip window)
    gemm_mma_kernel<<<mtiles, 256, SMEM_REQ>>>(px, pwh, pwl, pb, pz);                    // 3

    // 4-9: edge-index probe + CSR build (must precede first node_kernel)
    detect_kernel<<<1, 32>>>((const long long*)ei);                                      // 4
    zero_deg_kernel<<<nodeb, 256>>>();                                                   // 5
    count_deg_kernel<<<edgeb, 256>>>(ei);                                                // 6
    scan1_kernel<<<nodeb, 256>>>();                                                      // 7
    scan2_kernel<<<1, 512>>>(nodeb);                                                     // 8
    rowptr_kernel<<<nodeb, 256>>>();                                                     // 9
    scatter_kernel<<<edgeb, 256>>>(ei);                                                  // 10

    for (int l = 0; l < N_LAYERS; l++) {
        if (l > 0) {
            gemm_mma_kernel<<<mtiles, 256, SMEM_REQ>>>(
                px, pwh + (size_t)l * DZ * D, pwl + (size_t)l * DZ * D,
                pb + (size_t)l * DZ, pz);
        }
        float* dstp = (l == N_LAYERS - 1) ? out : px;
        node_kernel<<<(N_NODES + 7) / 8, 256>>>(dstp, l < N_LAYERS - 1 ? 1 : 0);
    }
}

// round 10
// speedup vs baseline: 2.8112x; 1.0609x over previous
#include <cuda_runtime.h>
#include <cuda_bf16.h>
#include <cstdint>

#define N_NODES 100000
#define N_EDGES 1600000
#define D       128
#define DZ      768          // fused output width: skip|beta_s|gamma_s|h|beta|gamma
#define N_LAYERS 4

// ---------------- scratch (device globals: no allocation allowed) ----------------
__device__ float g_x    [(size_t)N_NODES * D];
__device__ float g_z    [(size_t)N_NODES * DZ];
__device__ __nv_bfloat16 g_wthi[(size_t)N_LAYERS * DZ * D];   // W^T hi  [l][n][k]
__device__ __nv_bfloat16 g_wtlo[(size_t)N_LAYERS * DZ * D];   // W^T lo
__device__ float g_bpack[(size_t)N_LAYERS * DZ];
__device__ float g_deginv[N_NODES];
__device__ int   g_deg   [N_NODES];
__device__ int   g_scan  [N_NODES];
__device__ int   g_bsum  [512];
__device__ int   g_rowptr[N_NODES + 1];
__device__ int   g_fill  [N_NODES];
__device__ int   g_esrc  [N_EDGES];
__device__ int   g_is64;

// ---------------- PTX helpers ----------------
__device__ __forceinline__ uint32_t smem_u32(const void* p) {
    uint32_t a;
    asm("{ .reg .u64 t; cvta.to.shared.u64 t, %1; cvt.u32.u64 %0, t; }" : "=r"(a) : "l"(p));
    return a;
}
__device__ __forceinline__ void ldsm_x4(uint32_t addr, uint32_t* r) {
    asm volatile("ldmatrix.sync.aligned.m8n8.x4.shared.b16 {%0,%1,%2,%3}, [%4];"
                 : "=r"(r[0]), "=r"(r[1]), "=r"(r[2]), "=r"(r[3]) : "r"(addr));
}
__device__ __forceinline__ void mma_bf16(float* c, const uint32_t* a, const uint32_t* b) {
    asm volatile(
        "mma.sync.aligned.m16n8k16.row.col.f32.bf16.bf16.f32 "
        "{%0,%1,%2,%3}, {%4,%5,%6,%7}, {%8,%9}, {%0,%1,%2,%3};"
        : "+f"(c[0]), "+f"(c[1]), "+f"(c[2]), "+f"(c[3])
        : "r"(a[0]), "r"(a[1]), "r"(a[2]), "r"(a[3]), "r"(b[0]), "r"(b[1]));
}

// ---------------- edge-index dtype probe ----------------
__global__ void detect_kernel(const long long* __restrict__ ei) {
    if (threadIdx.x == 0 && blockIdx.x == 0) {
        int ok = 1;
        #pragma unroll
        for (int i = 0; i < 16; i++) {
            long long v = ei[i];
            if (v < 0 || v >= N_NODES) ok = 0;
        }
        g_is64 = ok;
    }
}
__device__ __forceinline__ int edge_at(const void* ei, size_t idx, int is64) {
    return is64 ? (int)((const long long*)ei)[idx] : ((const int*)ei)[idx];
}

// ---------------- degree + CSR build ----------------
__global__ void zero_deg_kernel() {
    int i = blockIdx.x * blockDim.x + threadIdx.x;
    if (i < N_NODES) g_deg[i] = 0;
}
__global__ void count_deg_kernel(const void* __restrict__ ei) {
    int e = blockIdx.x * blockDim.x + threadIdx.x;
    if (e < N_EDGES) atomicAdd(&g_deg[edge_at(ei, (size_t)N_EDGES + e, g_is64)], 1);
}
__global__ void scan1_kernel() {
    __shared__ int s[256];
    int tid = threadIdx.x, i = blockIdx.x * 256 + tid;
    int v = (i < N_NODES) ? g_deg[i] : 0;
    s[tid] = v; __syncthreads();
    #pragma unroll
    for (int off = 1; off < 256; off <<= 1) {
        int t = (tid >= off) ? s[tid - off] : 0;
        __syncthreads(); s[tid] += t; __syncthreads();
    }
    if (i < N_NODES) g_scan[i] = s[tid];
    if (tid == 255) g_bsum[blockIdx.x] = s[255];
}
__global__ void scan2_kernel(int nblk) {
    __shared__ int s[512];
    int tid = threadIdx.x;
    s[tid] = (tid < nblk) ? g_bsum[tid] : 0; __syncthreads();
    #pragma unroll
    for (int off = 1; off < 512; off <<= 1) {
        int t = (tid >= off) ? s[tid - off] : 0;
        __syncthreads(); s[tid] += t; __syncthreads();
    }
    if (tid < nblk) g_bsum[tid] = s[tid];
}
__global__ void rowptr_kernel() {
    int i = blockIdx.x * blockDim.x + threadIdx.x;
    if (i < N_NODES) {
        int blk = i >> 8;
        int off = (blk > 0) ? g_bsum[blk - 1] : 0;
        g_rowptr[i] = g_scan[i] - g_deg[i] + off;
        g_fill[i] = 0;
        g_deginv[i] = 1.0f / fmaxf((float)g_deg[i], 1.0f);
    }
    if (i == 0) g_rowptr[N_NODES] = N_EDGES;
}
__global__ void scatter_kernel(const void* __restrict__ ei) {
    int e = blockIdx.x * blockDim.x + threadIdx.x;
    if (e < N_EDGES) {
        int is64 = g_is64;
        int s = edge_at(ei, (size_t)e, is64);
        int d = edge_at(ei, (size_t)N_EDGES + e, is64);
        g_esrc[g_rowptr[d] + atomicAdd(&g_fill[d], 1)] = s;
    }
}
__global__ void copy_x_kernel(const float4* __restrict__ src) {
    int i = blockIdx.x * blockDim.x + threadIdx.x;
    if (i < N_NODES * (D / 4)) ((float4*)g_x)[i] = src[i];
}

// ---------------- weight packing: W^T hi/lo bf16 split -------------------------
// fused cols: [0,128)=W_skip [128,384)=W_fskip [384,512)=W_lin [512,768)=W_film
__global__ void wpack_kernel(const float* __restrict__ W_lin,
                             const float* __restrict__ W_film,
                             const float* __restrict__ W_skip,
                             const float* __restrict__ W_fskip) {
    int i = blockIdx.x * blockDim.x + threadIdx.x;   // [0, 4*768*128)
    if (i >= N_LAYERS * DZ * D) return;
    int k = i % D;
    int n = (i / D) % DZ;
    int l = i / (D * DZ);
    float v;
    if (n < 128)      v = W_skip [((size_t)l * D + k) * 128 + n];
    else if (n < 384) v = W_fskip[((size_t)l * D + k) * 256 + (n - 128)];
    else if (n < 512) v = W_lin  [((size_t)l * D + k) * 128 + (n - 384)];
    else              v = W_film [((size_t)l * D + k) * 256 + (n - 512)];
    __nv_bfloat16 hi = __float2bfloat16_rn(v);
    __nv_bfloat16 lo = __float2bfloat16_rn(v - __bfloat162float(hi));
    g_wthi[i] = hi;
    g_wtlo[i] = lo;
}
__global__ void bpack_kernel(const float* __restrict__ b_film) {
    int i = blockIdx.x * blockDim.x + threadIdx.x;
    if (i >= N_LAYERS * DZ) return;
    int c = i % DZ, l = i / DZ;
    g_bpack[i] = (c >= 512) ? b_film[(size_t)l * 256 + (c - 512)] : 0.0f;
}

// ---------------- mma.sync bf16 GEMM, CTA tile 128x256, warp tile 64x64 --------
// L1-bound fix: 16 LDSM.x4 feed 96 HMMA per K-step per warp (was 6:16).
// 3 split-combos fused in K-loop: Ahi*Bhi + Ahi*Blo + Alo*Bhi, fp32 accum.
// Smem rows: 128 k-elems bf16 = 256B = 16 chunks of 16B; chunk swizzle ^ (row&7).
#define OFF_AHI  0
#define OFF_ALO  32768
#define OFF_BHI  65536
#define OFF_BLO  131072
#define SMEM_REQ 196608
#define BN_CTA   256
#define NTILES   (DZ / BN_CTA)   // 3

__global__ __launch_bounds__(256, 1)
void gemm_mma_kernel(const float* __restrict__ A,
                     const __nv_bfloat16* __restrict__ Bhi,
                     const __nv_bfloat16* __restrict__ Blo,
                     const float* __restrict__ bias, float* __restrict__ C) {
    extern __shared__ char sm[];
    uint32_t sb = smem_u32(sm);
    int tid = threadIdx.x, wid = tid >> 5, lane = tid & 31;
    int row0 = blockIdx.x * 128;

    // ---- A loader (once): split fp32 -> bf16 hi/lo. thread = (row=tid/2, half=tid&1)
    {
        int r = tid >> 1, h = tid & 1;
        int grow = row0 + r;
        uint32_t rbase = r * 256;
        int r7 = r & 7;
        if (grow < N_NODES) {
            const float4* ap = (const float4*)(A + (size_t)grow * D + h * 64);
            #pragma unroll
            for (int it = 0; it < 8; it++) {
                float4 f0 = ap[it * 2], f1 = ap[it * 2 + 1];
                float f[8] = {f0.x, f0.y, f0.z, f0.w, f1.x, f1.y, f1.z, f1.w};
                __nv_bfloat16 hi8[8], lo8[8];
                #pragma unroll
                for (int q = 0; q < 8; q++) {
                    hi8[q] = __float2bfloat16_rn(f[q]);
                    lo8[q] = __float2bfloat16_rn(f[q] - __bfloat162float(hi8[q]));
                }
                int kc = h * 8 + it;
                uint32_t off = rbase + (uint32_t)((kc ^ r7) << 4);
                *(uint4*)(sm + OFF_AHI + off) = *(const uint4*)hi8;
                *(uint4*)(sm + OFF_ALO + off) = *(const uint4*)lo8;
            }
        } else {
            uint4 z = make_uint4(0, 0, 0, 0);
            #pragma unroll
            for (int it = 0; it < 8; it++) {
                int kc = h * 8 + it;
                uint32_t off = rbase + (uint32_t)((kc ^ r7) << 4);
                *(uint4*)(sm + OFF_AHI + off) = z;
                *(uint4*)(sm + OFF_ALO + off) = z;
            }
        }
    }

    // warp grid: 2 (M) x 4 (N); warp tile 64 rows x 64 cols
    const int warpM = wid & 1, warpN = wid >> 1;
    const int laneA_m   = lane & 15;
    const int laneA_kad = lane >> 4;                       // 0/1
    const int laneB_n   = (lane & 7) + ((lane & 16) ? 8 : 0);
    const int laneB_kad = (lane >> 3) & 1;

    const int bld_r  = tid;                                // B loader: one row/thread
    const uint32_t bld_nb = bld_r * 256;
    const int bld_r7 = bld_r & 7;

    #pragma unroll 1
    for (int nt = 0; nt < NTILES; nt++) {
        const int n0 = nt * BN_CTA;

        // ---- load B tile (256 rows, hi+lo)
        {
            const uint4* bh = (const uint4*)(Bhi + (size_t)(n0 + bld_r) * D);
            const uint4* bl = (const uint4*)(Blo + (size_t)(n0 + bld_r) * D);
            #pragma unroll
            for (int kc = 0; kc < 16; kc++) {
                uint32_t off = bld_nb + (uint32_t)((kc ^ bld_r7) << 4);
                *(uint4*)(sm + OFF_BHI + off) = bh[kc];
                *(uint4*)(sm + OFF_BLO + off) = bl[kc];
            }
        }
        __syncthreads();

        float acc[4][8][4];
        #pragma unroll
        for (int mt = 0; mt < 4; mt++)
            #pragma unroll
            for (int g = 0; g < 8; g++)
                #pragma unroll
                for (int q = 0; q < 4; q++) acc[mt][g][q] = 0.0f;

        #pragma unroll
        for (int ks = 0; ks < 8; ks++) {
            // A fragments: 4 m16 tiles, hi + lo
            uint32_t ah[4][4], al[4][4];
            #pragma unroll
            for (int mt = 0; mt < 4; mt++) {
                int m = warpM * 64 + mt * 16 + laneA_m;
                int kc = ks * 2 + laneA_kad;
                uint32_t soff = (uint32_t)(m * 256 + (((kc ^ (m & 7))) << 4));
                ldsm_x4(sb + OFF_AHI + soff, ah[mt]);
                ldsm_x4(sb + OFF_ALO + soff, al[mt]);
            }
            // B fragments: 4 n16 groups -> 8 n8 frags, hi + lo
            uint32_t bh[8][2], bl[8][2];
            #pragma unroll
            for (int g = 0; g < 4; g++) {
                int n = warpN * 64 + g * 16 + laneB_n;
                int kc = ks * 2 + laneB_kad;
                uint32_t soff = (uint32_t)(n * 256 + (((kc ^ (n & 7))) << 4));
                uint32_t r[4];
                ldsm_x4(sb + OFF_BHI + soff, r);
                bh[g * 2][0] = r[0]; bh[g * 2][1] = r[1];
                bh[g * 2 + 1][0] = r[2]; bh[g * 2 + 1][1] = r[3];
                ldsm_x4(sb + OFF_BLO + soff, r);
                bl[g * 2][0] = r[0]; bl[g * 2][1] = r[1];
                bl[g * 2 + 1][0] = r[2]; bl[g * 2 + 1][1] = r[3];
            }
            // 3 split combos x 32 MMAs
            #pragma unroll
            for (int mt = 0; mt < 4; mt++)
                #pragma unroll
                for (int g = 0; g < 8; g++) {
                    mma_bf16(acc[mt][g], ah[mt], bh[g]);
                    mma_bf16(acc[mt][g], ah[mt], bl[g]);
                    mma_bf16(acc[mt][g], al[mt], bh[g]);
                }
        }

        // ---- epilogue: c0,c1 -> (row, col..col+1); c2,c3 -> (row+8)
        int rbase = row0 + warpM * 64 + (lane >> 2);
        int cbase = n0 + warpN * 64 + (lane & 3) * 2;
        #pragma unroll
        for (int mt = 0; mt < 4; mt++) {
            #pragma unroll
            for (int g = 0; g < 8; g++) {
                int col = cbase + g * 8;
                float b0 = bias[col], b1 = bias[col + 1];
                int r1 = rbase + mt * 16;
                if (r1 < N_NODES) {
                    float2 v = make_float2(acc[mt][g][0] + b0, acc[mt][g][1] + b1);
                    *(float2*)(C + (size_t)r1 * DZ + col) = v;
                }
                int r2 = r1 + 8;
                if (r2 < N_NODES) {
                    float2 v = make_float2(acc[mt][g][2] + b0, acc[mt][g][3] + b1);
                    *(float2*)(C + (size_t)r2 * DZ + col) = v;
                }
            }
        }
        __syncthreads();   // B buffer reused next iteration
    }
}

// ---------------- fused node kernel: self-FiLM + CSR aggregation + finalize -----
// One warp per node; 4-way edge unroll. z row (float4 units, 192/row):
// skip@0 beta_s@32 gamma_s@64 h@96 beta@128 gamma@160.
__global__ __launch_bounds__(256)
void node_kernel(float* __restrict__ dstp, int do_relu) {
    int n = blockIdx.x * 8 + (threadIdx.x >> 5);
    if (n >= N_NODES) return;
    int lane = threadIdx.x & 31;
    const float4* z4 = (const float4*)g_z;
    size_t rb = (size_t)n * 192;

    float4 skip = z4[rb + lane];
    float4 bs   = z4[rb + 32 + lane];
    float4 gs   = z4[rb + 64 + lane];
    float4 be   = z4[rb + 128 + lane];
    float4 ga   = z4[rb + 160 + lane];

    float4 acc = make_float4(0.f, 0.f, 0.f, 0.f);
    int e  = g_rowptr[n];
    int e1 = g_rowptr[n + 1];
    for (; e + 3 < e1; e += 4) {
        int s0 = g_esrc[e];
        int s1 = g_esrc[e + 1];
        int s2 = g_esrc[e + 2];
        int s3 = g_esrc[e + 3];
        float4 h0 = z4[(size_t)s0 * 192 + 96 + lane];
        float4 h1 = z4[(size_t)s1 * 192 + 96 + lane];
        float4 h2 = z4[(size_t)s2 * 192 + 96 + lane];
        float4 h3 = z4[(size_t)s3 * 192 + 96 + lane];
        acc.x += fmaxf(fmaf(ga.x, h0.x, be.x), 0.f) + fmaxf(fmaf(ga.x, h1.x, be.x), 0.f)
               + fmaxf(fmaf(ga.x, h2.x, be.x), 0.f) + fmaxf(fmaf(ga.x, h3.x, be.x), 0.f);
        acc.y += fmaxf(fmaf(ga.y, h0.y, be.y), 0.f) + fmaxf(fmaf(ga.y, h1.y, be.y), 0.f)
               + fmaxf(fmaf(ga.y, h2.y, be.y), 0.f) + fmaxf(fmaf(ga.y, h3.y, be.y), 0.f);
        acc.z += fmaxf(fmaf(ga.z, h0.z, be.z), 0.f) + fmaxf(fmaf(ga.z, h1.z, be.z), 0.f)
               + fmaxf(fmaf(ga.z, h2.z, be.z), 0.f) + fmaxf(fmaf(ga.z, h3.z, be.z), 0.f);
        acc.w += fmaxf(fmaf(ga.w, h0.w, be.w), 0.f) + fmaxf(fmaf(ga.w, h1.w, be.w), 0.f)
               + fmaxf(fmaf(ga.w, h2.w, be.w), 0.f) + fmaxf(fmaf(ga.w, h3.w, be.w), 0.f);
    }
    for (; e < e1; e++) {
        int s0 = g_esrc[e];
        float4 h0 = z4[(size_t)s0 * 192 + 96 + lane];
        acc.x += fmaxf(fmaf(ga.x, h0.x, be.x), 0.f);
        acc.y += fmaxf(fmaf(ga.y, h0.y, be.y), 0.f);
        acc.z += fmaxf(fmaf(ga.z, h0.z, be.z), 0.f);
        acc.w += fmaxf(fmaf(ga.w, h0.w, be.w), 0.f);
    }

    float di = g_deginv[n];
    float4 o;
    o.x = fmaxf(fmaf(gs.x, skip.x, bs.x), 0.f) + acc.x * di;
    o.y = fmaxf(fmaf(gs.y, skip.y, bs.y), 0.f) + acc.y * di;
    o.z = fmaxf(fmaf(gs.z, skip.z, bs.z), 0.f) + acc.z * di;
    o.w = fmaxf(fmaf(gs.w, skip.w, bs.w), 0.f) + acc.w * di;
    if (do_relu) {
        o.x = fmaxf(o.x, 0.f); o.y = fmaxf(o.y, 0.f);
        o.z = fmaxf(o.z, 0.f); o.w = fmaxf(o.w, 0.f);
    }
    ((float4*)dstp)[(size_t)n * 32 + lane] = o;
}

// ---------------- launch --------------------------------------------------------
// gemm at launch index 3 (ncu skip window observed to land there).
// gemm prereqs: copy_x, wpack, bpack. detect/CSR only needed before node_kernel.
extern "C" void kernel_launch(void* const* d_in, const int* in_sizes, int n_in,
                              void* d_out, int out_size) {
    const float* x_in    = (const float*)d_in[0];
    const void*  ei      = d_in[1];
    const float* W_lin   = (const float*)d_in[2];
    const float* W_film  = (const float*)d_in[3];
    const float* b_film  = (const float*)d_in[4];
    const float* W_skip  = (const float*)d_in[5];
    const float* W_fskip = (const float*)d_in[6];
    float*       out     = (float*)d_out;

    float *px, *pz, *pb;
    __nv_bfloat16 *pwh, *pwl;
    cudaGetSymbolAddress((void**)&px,  g_x);
    cudaGetSymbolAddress((void**)&pz,  g_z);
    cudaGetSymbolAddress((void**)&pwh, g_wthi);
    cudaGetSymbolAddress((void**)&pwl, g_wtlo);
    cudaGetSymbolAddress((void**)&pb,  g_bpack);

    cudaFuncSetAttribute(gemm_mma_kernel, cudaFuncAttributeMaxDynamicSharedMemorySize, SMEM_REQ);

    const int nvec = N_NODES * (D / 4);
    const int vblocks = (nvec + 255) / 256;
    const int nodeb = (N_NODES + 255) / 256;      // 391
    const int edgeb = (N_EDGES + 255) / 256;      // 6250
    const int mtiles = (N_NODES + 127) / 128;     // 782

    // 0-2: prerequisites of the first GEMM
    copy_x_kernel<<<vblocks, 256>>>((const float4*)x_in);                                // 0
    wpack_kernel<<<(N_LAYERS * DZ * D + 255) / 256, 256>>>(W_lin, W_film, W_skip, W_fskip); // 1
    bpack_kernel<<<(N_LAYERS * DZ + 255) / 256, 256>>>(b_film);                          // 2

    // 3: first-layer GEMM (target of ncu skip window)
    gemm_mma_kernel<<<mtiles, 256, SMEM_REQ>>>(px, pwh, pwl, pb, pz);                    // 3

    // 4-10: edge-index probe + CSR build (must precede first node_kernel)
    detect_kernel<<<1, 32>>>((const long long*)ei);                                      // 4
    zero_deg_kernel<<<nodeb, 256>>>();                                                   // 5
    count_deg_kernel<<<edgeb, 256>>>(ei);                                                // 6
    scan1_kernel<<<nodeb, 256>>>();                                                      // 7
    scan2_kernel<<<1, 512>>>(nodeb);                                                     // 8
    rowptr_kernel<<<nodeb, 256>>>();                                                     // 9
    scatter_kernel<<<edgeb, 256>>>(ei);                                                  // 10

    for (int l = 0; l < N_LAYERS; l++) {
        if (l > 0) {
            gemm_mma_kernel<<<mtiles, 256, SMEM_REQ>>>(
                px, pwh + (size_t)l * DZ * D, pwl + (size_t)l * DZ * D,
                pb + (size_t)l * DZ, pz);
        }
        float* dstp = (l == N_LAYERS - 1) ? out : px;
        node_kernel<<<(N_NODES + 7) / 8, 256>>>(dstp, l < N_LAYERS - 1 ? 1 : 0);
    }
}